// round 4
// baseline (speedup 1.0000x reference)
#include <cuda_runtime.h>
#include <cuda_bf16.h>
#include <math.h>
#include <stdint.h>

// Problem constants
#define Bb   4
#define Lt   1024
#define Ct   1024
#define Ht   16
#define Dt   64
#define FFt  4096
#define NTOK (Bb * Lt)
#define SCALE 0.08838834764831843f

// ---------------- scratch (static device allocations; allowed) ----------------
static __device__ float g_q   [(size_t)NTOK * Ct];
static __device__ float g_k   [(size_t)NTOK * Ct];
static __device__ float g_v   [(size_t)NTOK * Ct];
static __device__ float g_attn[(size_t)NTOK * Ct];
static __device__ float g_proj[(size_t)NTOK * Ct];
static __device__ float g_x1  [(size_t)NTOK * Ct];
static __device__ float g_ff  [(size_t)NTOK * FFt];
static __device__ float g_sc  [(size_t)Bb * Ht * Lt * Lt];

// split-bf16 activations (aligned for 16B cp.async)
static __device__ __align__(256) __nv_bfloat16 g_hh[(size_t)NTOK * Ct],  g_hl[(size_t)NTOK * Ct];
static __device__ __align__(256) __nv_bfloat16 g_ah[(size_t)NTOK * Ct],  g_al[(size_t)NTOK * Ct];
static __device__ __align__(256) __nv_bfloat16 g_fh[(size_t)NTOK * FFt], g_fl[(size_t)NTOK * FFt];
// split-bf16 weights
static __device__ __align__(256) __nv_bfloat16 g_wqh[(size_t)Ct * Ct],  g_wql[(size_t)Ct * Ct];
static __device__ __align__(256) __nv_bfloat16 g_wkh[(size_t)Ct * Ct],  g_wkl[(size_t)Ct * Ct];
static __device__ __align__(256) __nv_bfloat16 g_wvh[(size_t)Ct * Ct],  g_wvl[(size_t)Ct * Ct];
static __device__ __align__(256) __nv_bfloat16 g_woh[(size_t)Ct * Ct],  g_wol[(size_t)Ct * Ct];
static __device__ __align__(256) __nv_bfloat16 g_w1h[(size_t)FFt * Ct], g_w1l[(size_t)FFt * Ct];
static __device__ __align__(256) __nv_bfloat16 g_w2h[(size_t)Ct * FFt], g_w2l[(size_t)Ct * FFt];

__device__ __forceinline__ float gelu_exact(float x) {
    return 0.5f * x * (1.0f + erff(x * 0.70710678118654752f));
}

__device__ __forceinline__ uint32_t smem_u32(const void* p) {
    uint32_t a;
    asm("{ .reg .u64 t; cvta.to.shared.u64 t, %1; cvt.u32.u64 %0, t; }" : "=r"(a) : "l"(p));
    return a;
}

// ---------------- HMMA GEMM building blocks (base sm_103 features only) -------
#define LDMX4(d0, d1, d2, d3, addr) \
    asm volatile("ldmatrix.sync.aligned.m8n8.x4.shared.b16 {%0,%1,%2,%3}, [%4];" \
                 : "=r"(d0), "=r"(d1), "=r"(d2), "=r"(d3) : "r"(addr))

#define MMA16816(d, a, b) \
    asm volatile("mma.sync.aligned.m16n8k16.row.col.f32.bf16.bf16.f32 " \
                 "{%0,%1,%2,%3}, {%4,%5,%6,%7}, {%8,%9}, {%0,%1,%2,%3};" \
                 : "+f"((d)[0]), "+f"((d)[1]), "+f"((d)[2]), "+f"((d)[3]) \
                 : "r"((a)[0]), "r"((a)[1]), "r"((a)[2]), "r"((a)[3]), \
                   "r"((b)[0]), "r"((b)[1]))

#define CPASYNC16(saddr, gptr) \
    asm volatile("cp.async.cg.shared.global [%0], [%1], 16;" :: "r"(saddr), "l"(gptr))
#define CPCOMMIT() asm volatile("cp.async.commit_group;")
#define CPWAIT1()  asm volatile("cp.async.wait_group 1;")
#define CPWAIT0()  asm volatile("cp.async.wait_group 0;")

// 128 rows x 32 cols bf16 matrix in smem: 64B rows split into 4x16B segs,
// seg' = s ^ ((r>>1)&3)  -> conflict-free ldmatrix & stores.
__device__ __forceinline__ uint32_t swz(int r, int s) {
    return (uint32_t)(r * 64 + ((s ^ ((r >> 1) & 3)) << 4));
}

// stage layout: Ah @0, Al @8192, Bh @16384, Bl @24576 ; stage = 32768 B
#define STAGE 32768
#define GEMM_SMEM (2 * STAGE)

enum { EPI_BIAS = 0, EPI_GELU = 1, EPI_RES = 2 };

template <int EPI>
__global__ __launch_bounds__(256) void hmma_gemm(
    const __nv_bfloat16* __restrict__ Ah, const __nv_bfloat16* __restrict__ Al,
    const __nv_bfloat16* __restrict__ Bh, const __nv_bfloat16* __restrict__ Bl,
    const float* __restrict__ bias, const float* __restrict__ res,
    float* __restrict__ C, int N, int K)
{
    extern __shared__ __align__(128) char smem[];
    const uint32_t sb = smem_u32(smem);
    const int tid  = threadIdx.x;
    const int lane = tid & 31;
    const int wid  = tid >> 5;
    const int wm   = (wid & 1) * 64;     // warp m-offset (2 warps over M)
    const int wn   = (wid >> 1) * 32;    // warp n-offset (4 warps over N)

    const __nv_bfloat16* gAh = Ah + (size_t)blockIdx.y * 128 * K;
    const __nv_bfloat16* gAl = Al + (size_t)blockIdx.y * 128 * K;
    const __nv_bfloat16* gBh = Bh + (size_t)blockIdx.x * 128 * K;
    const __nv_bfloat16* gBl = Bl + (size_t)blockIdx.x * 128 * K;

    const int nch = K >> 5;

    // per-thread global/smem load mapping: 2 segs of 16B per matrix per chunk
    const int r0 = tid >> 2,          s0 = tid & 3;
    const int r1 = (tid + 256) >> 2;  // s1 == s0
    const uint32_t sw0 = swz(r0, s0);
    const uint32_t sw1 = swz(r1, s0);
    const size_t go0 = (size_t)r0 * K + s0 * 8;
    const size_t go1 = (size_t)r1 * K + s0 * 8;

#define ISSUE(c)                                                              \
    do {                                                                      \
        const uint32_t bs_ = sb + ((c) & 1) * STAGE;                          \
        const size_t kof_ = (size_t)(c) * 32;                                 \
        CPASYNC16(bs_ + 0     + sw0, gAh + go0 + kof_);                       \
        CPASYNC16(bs_ + 0     + sw1, gAh + go1 + kof_);                       \
        CPASYNC16(bs_ + 8192  + sw0, gAl + go0 + kof_);                       \
        CPASYNC16(bs_ + 8192  + sw1, gAl + go1 + kof_);                       \
        CPASYNC16(bs_ + 16384 + sw0, gBh + go0 + kof_);                       \
        CPASYNC16(bs_ + 16384 + sw1, gBh + go1 + kof_);                       \
        CPASYNC16(bs_ + 24576 + sw0, gBl + go0 + kof_);                       \
        CPASYNC16(bs_ + 24576 + sw1, gBl + go1 + kof_);                       \
        CPCOMMIT();                                                           \
    } while (0)

    ISSUE(0);
    ISSUE(1);

    float acc[4][4][4];
#pragma unroll
    for (int i = 0; i < 4; i++)
#pragma unroll
        for (int j = 0; j < 4; j++)
#pragma unroll
            for (int t = 0; t < 4; t++) acc[i][j][t] = 0.0f;

    for (int c = 0; c < nch; c++) {
        if (c < nch - 1) CPWAIT1(); else CPWAIT0();
        __syncthreads();
        const uint32_t base = sb + (c & 1) * STAGE;

#pragma unroll
        for (int ks = 0; ks < 2; ks++) {
            uint32_t ah[4][4], al_[4][4], bh[4][2], bl_[4][2];
            const int ar  = wm + (lane & 15);
            const int as_ = ks * 2 + (lane >> 4);
#pragma unroll
            for (int mi = 0; mi < 4; mi++) {
                uint32_t ad = base + swz(ar + mi * 16, as_);
                LDMX4(ah[mi][0], ah[mi][1], ah[mi][2], ah[mi][3], ad);
                uint32_t ad2 = base + 8192 + swz(ar + mi * 16, as_);
                LDMX4(al_[mi][0], al_[mi][1], al_[mi][2], al_[mi][3], ad2);
            }
            const int br = wn + ((lane >> 4) & 1) * 8 + (lane & 7);
            const int bs2 = ks * 2 + ((lane >> 3) & 1);
#pragma unroll
            for (int np = 0; np < 2; np++) {
                uint32_t bd = base + 16384 + swz(br + np * 16, bs2);
                LDMX4(bh[np * 2][0], bh[np * 2][1], bh[np * 2 + 1][0], bh[np * 2 + 1][1], bd);
                uint32_t bd2 = base + 24576 + swz(br + np * 16, bs2);
                LDMX4(bl_[np * 2][0], bl_[np * 2][1], bl_[np * 2 + 1][0], bl_[np * 2 + 1][1], bd2);
            }
#pragma unroll
            for (int mi = 0; mi < 4; mi++)
#pragma unroll
                for (int nt = 0; nt < 4; nt++) MMA16816(acc[mi][nt], ah[mi], bh[nt]);
#pragma unroll
            for (int mi = 0; mi < 4; mi++)
#pragma unroll
                for (int nt = 0; nt < 4; nt++) MMA16816(acc[mi][nt], ah[mi], bl_[nt]);
#pragma unroll
            for (int mi = 0; mi < 4; mi++)
#pragma unroll
                for (int nt = 0; nt < 4; nt++) MMA16816(acc[mi][nt], al_[mi], bh[nt]);
        }

        __syncthreads();
        if (c + 2 < nch) ISSUE(c + 2);
    }
#undef ISSUE

    // epilogue
    const int rbase = blockIdx.y * 128 + wm + (lane >> 2);
    const int cbase = blockIdx.x * 128 + wn + (lane & 3) * 2;
#pragma unroll
    for (int mi = 0; mi < 4; mi++) {
#pragma unroll
        for (int half = 0; half < 2; half++) {
            const int row = rbase + mi * 16 + half * 8;
            const size_t ro = (size_t)row * N;
#pragma unroll
            for (int nt = 0; nt < 4; nt++) {
                const int col = cbase + nt * 8;
                float v0 = acc[mi][nt][half * 2 + 0] + bias[col];
                float v1 = acc[mi][nt][half * 2 + 1] + bias[col + 1];
                if (EPI == EPI_GELU) { v0 = gelu_exact(v0); v1 = gelu_exact(v1); }
                if (EPI == EPI_RES)  { v0 += res[ro + col]; v1 += res[ro + col + 1]; }
                C[ro + col]     = v0;
                C[ro + col + 1] = v1;
            }
        }
    }
}

// ---------------- fp32 -> split bf16 (hi/lo) ----------------
__global__ __launch_bounds__(256) void split_bf16_kernel(
    const float* __restrict__ s, __nv_bfloat16* __restrict__ hi,
    __nv_bfloat16* __restrict__ lo, int n4)
{
    int i = blockIdx.x * 256 + threadIdx.x;
    if (i >= n4) return;
    float4 v = ((const float4*)s)[i];
    float vv[4] = {v.x, v.y, v.z, v.w};
#pragma unroll
    for (int k = 0; k < 4; k++) {
        __nv_bfloat16 h = __float2bfloat16(vv[k]);
        __nv_bfloat16 l = __float2bfloat16(vv[k] - __bfloat162float(h));
        hi[(size_t)i * 4 + k] = h;
        lo[(size_t)i * 4 + k] = l;
    }
}

// ---------------- layernorm -> split bf16 ----------------
__global__ __launch_bounds__(256) void ln_bf16_kernel(
    const float* __restrict__ in, const float* __restrict__ g, const float* __restrict__ be,
    __nv_bfloat16* __restrict__ hi, __nv_bfloat16* __restrict__ lo, int cols)
{
    const size_t base = (size_t)blockIdx.x * cols;
    const int tid = threadIdx.x;
    __shared__ float rs[32], rs2[32];

    float s = 0.0f, s2 = 0.0f;
    for (int c = tid; c < cols; c += 256) {
        float x = in[base + c];
        s += x; s2 += x * x;
    }
#pragma unroll
    for (int o = 16; o; o >>= 1) {
        s  += __shfl_xor_sync(0xffffffffu, s,  o);
        s2 += __shfl_xor_sync(0xffffffffu, s2, o);
    }
    if ((tid & 31) == 0) { rs[tid >> 5] = s; rs2[tid >> 5] = s2; }
    __syncthreads();
    if (tid == 0) {
        float a = 0.0f, a2 = 0.0f;
        for (int i = 0; i < 8; i++) { a += rs[i]; a2 += rs2[i]; }
        rs[0] = a; rs2[0] = a2;
    }
    __syncthreads();
    const float icols = 1.0f / (float)cols;
    const float mean = rs[0] * icols;
    const float var  = rs2[0] * icols - mean * mean;
    const float rstd = rsqrtf(var + 1e-5f);

    for (int c = tid; c < cols; c += 256) {
        float x = in[base + c];
        float val = (x - mean) * rstd * g[c] + be[c];
        __nv_bfloat16 h = __float2bfloat16(val);
        hi[base + c] = h;
        lo[base + c] = __float2bfloat16(val - __bfloat162float(h));
    }
}

// ---------------- layernorm fp32 (+residual) ----------------
template <bool RES>
__global__ __launch_bounds__(256) void ln_kernel(
    const float* __restrict__ in, const float* __restrict__ g, const float* __restrict__ be,
    const float* __restrict__ res, float* __restrict__ out, int cols)
{
    const size_t base = (size_t)blockIdx.x * cols;
    const int tid = threadIdx.x;
    __shared__ float rs[32], rs2[32];

    float s = 0.0f, s2 = 0.0f;
    for (int c = tid; c < cols; c += 256) {
        float x = in[base + c];
        s += x; s2 += x * x;
    }
#pragma unroll
    for (int o = 16; o; o >>= 1) {
        s  += __shfl_xor_sync(0xffffffffu, s,  o);
        s2 += __shfl_xor_sync(0xffffffffu, s2, o);
    }
    if ((tid & 31) == 0) { rs[tid >> 5] = s; rs2[tid >> 5] = s2; }
    __syncthreads();
    if (tid == 0) {
        float a = 0.0f, a2 = 0.0f;
        for (int i = 0; i < 8; i++) { a += rs[i]; a2 += rs2[i]; }
        rs[0] = a; rs2[0] = a2;
    }
    __syncthreads();
    const float icols = 1.0f / (float)cols;
    const float mean = rs[0] * icols;
    const float var  = rs2[0] * icols - mean * mean;
    const float rstd = rsqrtf(var + 1e-5f);

    for (int c = tid; c < cols; c += 256) {
        float x = in[base + c];
        float val = (x - mean) * rstd * g[c] + be[c];
        if (RES) val += res[base + c];
        out[base + c] = val;
    }
}

// ---------------- attention scores: S = scale*Q@K^T + bias + mask ----------------
__global__ __launch_bounds__(256) void attn_scores_kernel(
    const float* __restrict__ q, const float* __restrict__ k,
    const float* __restrict__ bias, const float* __restrict__ mask,
    float* __restrict__ S)
{
    __shared__ float As[8][128];
    __shared__ float Bs[8][128];
    const int tid  = threadIdx.x;
    const int tx   = tid & 15;
    const int ty   = tid >> 4;
    const int lRow = tid >> 1;
    const int lCol = (tid & 1) << 2;

    const int bh = blockIdx.z;
    const int b  = bh >> 4;
    const int h  = bh & 15;

    const float* Ab  = q + (size_t)b * Lt * Ct + h * Dt + (size_t)blockIdx.y * 128 * Ct;
    const float* Bbp = k + (size_t)b * Lt * Ct + h * Dt + (size_t)blockIdx.x * 128 * Ct;

    float acc[8][8];
#pragma unroll
    for (int i = 0; i < 8; i++)
#pragma unroll
        for (int j = 0; j < 8; j++) acc[i][j] = 0.0f;

    for (int k0 = 0; k0 < Dt; k0 += 8) {
        float4 a4 = *reinterpret_cast<const float4*>(Ab  + (size_t)lRow * Ct + k0 + lCol);
        float4 b4 = *reinterpret_cast<const float4*>(Bbp + (size_t)lRow * Ct + k0 + lCol);
        __syncthreads();
        As[lCol + 0][lRow] = a4.x; As[lCol + 1][lRow] = a4.y;
        As[lCol + 2][lRow] = a4.z; As[lCol + 3][lRow] = a4.w;
        Bs[lCol + 0][lRow] = b4.x; Bs[lCol + 1][lRow] = b4.y;
        Bs[lCol + 2][lRow] = b4.z; Bs[lCol + 3][lRow] = b4.w;
        __syncthreads();
#pragma unroll
        for (int kk = 0; kk < 8; kk++) {
            float4 a0 = *reinterpret_cast<const float4*>(&As[kk][ty * 8]);
            float4 a1 = *reinterpret_cast<const float4*>(&As[kk][ty * 8 + 4]);
            float4 b0 = *reinterpret_cast<const float4*>(&Bs[kk][tx * 8]);
            float4 b1 = *reinterpret_cast<const float4*>(&Bs[kk][tx * 8 + 4]);
            float a[8] = {a0.x, a0.y, a0.z, a0.w, a1.x, a1.y, a1.z, a1.w};
            float bv[8] = {b0.x, b0.y, b0.z, b0.w, b1.x, b1.y, b1.z, b1.w};
#pragma unroll
            for (int i = 0; i < 8; i++)
#pragma unroll
                for (int j = 0; j < 8; j++) acc[i][j] = fmaf(a[i], bv[j], acc[i][j]);
        }
    }

    const size_t sbs = (size_t)bh * Lt * Lt;
    const size_t mb  = (size_t)b * Lt * Lt;
    const int row0 = blockIdx.y * 128 + ty * 8;
    const int col0 = blockIdx.x * 128 + tx * 8;
#pragma unroll
    for (int i = 0; i < 8; i++) {
        size_t ro = (size_t)(row0 + i) * Lt + col0;
#pragma unroll
        for (int j = 0; j < 8; j++)
            S[sbs + ro + j] = acc[i][j] * SCALE + bias[sbs + ro + j] + mask[mb + ro + j];
    }
}

// ---------------- softmax over last dim (L=1024), in-place ----------------
__global__ __launch_bounds__(256) void softmax_kernel(float* __restrict__ S)
{
    const size_t base = (size_t)blockIdx.x * Lt;
    const int tid = threadIdx.x;
    __shared__ float red[32];

    float v[4];
    float mx = -1e30f;
#pragma unroll
    for (int i = 0; i < 4; i++) { v[i] = S[base + tid + i * 256]; mx = fmaxf(mx, v[i]); }
#pragma unroll
    for (int o = 16; o; o >>= 1) mx = fmaxf(mx, __shfl_xor_sync(0xffffffffu, mx, o));
    if ((tid & 31) == 0) red[tid >> 5] = mx;
    __syncthreads();
    if (tid == 0) {
        float m = red[0];
        for (int i = 1; i < 8; i++) m = fmaxf(m, red[i]);
        red[0] = m;
    }
    __syncthreads();
    mx = red[0];

    float s = 0.0f;
#pragma unroll
    for (int i = 0; i < 4; i++) { v[i] = __expf(v[i] - mx); s += v[i]; }
#pragma unroll
    for (int o = 16; o; o >>= 1) s += __shfl_xor_sync(0xffffffffu, s, o);
    __syncthreads();
    if ((tid & 31) == 0) red[tid >> 5] = s;
    __syncthreads();
    if (tid == 0) {
        float t = 0.0f;
        for (int i = 0; i < 8; i++) t += red[i];
        red[0] = t;
    }
    __syncthreads();
    const float inv = 1.0f / red[0];
#pragma unroll
    for (int i = 0; i < 4; i++) S[base + tid + i * 256] = v[i] * inv;
}

// ---------------- attn output: O = P @ V_head, scaled by c_attn[h] -------------
__global__ __launch_bounds__(256) void attn_pv_kernel(
    const float* __restrict__ S, const float* __restrict__ v,
    const float* __restrict__ c_attn, float* __restrict__ out)
{
    __shared__ float Ps[16][64];
    __shared__ float Vs[16][68];
    const int tid = threadIdx.x;
    const int tx = tid & 15;
    const int ty = tid >> 4;
    const int pRow = tid >> 2;
    const int pCol = (tid & 3) << 2;
    const int vRow = tid >> 4;
    const int vCol = (tid & 15) << 2;

    const int bh = blockIdx.y;
    const int b  = bh >> 4;
    const int h  = bh & 15;

    const float* Pb = S + (size_t)bh * Lt * Lt + (size_t)blockIdx.x * 64 * Lt;
    const float* Vb = v + (size_t)b * Lt * Ct + h * Dt;

    float acc[4][4];
#pragma unroll
    for (int i = 0; i < 4; i++)
#pragma unroll
        for (int j = 0; j < 4; j++) acc[i][j] = 0.0f;

    for (int k0 = 0; k0 < Lt; k0 += 16) {
        float4 p4 = *reinterpret_cast<const float4*>(Pb + (size_t)pRow * Lt + k0 + pCol);
        float4 v4 = *reinterpret_cast<const float4*>(Vb + (size_t)(k0 + vRow) * Ct + vCol);
        __syncthreads();
        Ps[pCol + 0][pRow] = p4.x; Ps[pCol + 1][pRow] = p4.y;
        Ps[pCol + 2][pRow] = p4.z; Ps[pCol + 3][pRow] = p4.w;
        Vs[vRow][vCol + 0] = v4.x; Vs[vRow][vCol + 1] = v4.y;
        Vs[vRow][vCol + 2] = v4.z; Vs[vRow][vCol + 3] = v4.w;
        __syncthreads();
#pragma unroll
        for (int kk = 0; kk < 16; kk++) {
            float a[4] = {Ps[kk][ty * 4 + 0], Ps[kk][ty * 4 + 1],
                          Ps[kk][ty * 4 + 2], Ps[kk][ty * 4 + 3]};
            float bvv[4] = {Vs[kk][tx * 4 + 0], Vs[kk][tx * 4 + 1],
                            Vs[kk][tx * 4 + 2], Vs[kk][tx * 4 + 3]};
#pragma unroll
            for (int i = 0; i < 4; i++)
#pragma unroll
                for (int j = 0; j < 4; j++) acc[i][j] = fmaf(a[i], bvv[j], acc[i][j]);
        }
    }

    const float cs = c_attn[h];
    const int row0 = blockIdx.x * 64 + ty * 4;
    const int col0 = tx * 4;
#pragma unroll
    for (int i = 0; i < 4; i++)
#pragma unroll
        for (int j = 0; j < 4; j++)
            out[((size_t)b * Lt + row0 + i) * Ct + h * Dt + col0 + j] = acc[i][j] * cs;
}

// ---------------- launch ----------------
extern "C" void kernel_launch(void* const* d_in, const int* in_sizes, int n_in,
                              void* d_out, int out_size)
{
    const float* x       = (const float*)d_in[0];
    const float* ab      = (const float*)d_in[1];
    const float* amask   = (const float*)d_in[2];
    const float* Wq      = (const float*)d_in[3];
    const float* bq      = (const float*)d_in[4];
    const float* Wk      = (const float*)d_in[5];
    const float* bk      = (const float*)d_in[6];
    const float* Wv      = (const float*)d_in[7];
    const float* bv      = (const float*)d_in[8];
    const float* Wo      = (const float*)d_in[9];
    const float* bo      = (const float*)d_in[10];
    const float* c_attn  = (const float*)d_in[11];
    const float* W1      = (const float*)d_in[12];
    const float* b1      = (const float*)d_in[13];
    const float* W2      = (const float*)d_in[14];
    const float* b2      = (const float*)d_in[15];
    const float* ln_g    = (const float*)d_in[16];
    const float* ln_b    = (const float*)d_in[17];
    const float* mln_g   = (const float*)d_in[18];
    const float* mln_b   = (const float*)d_in[19];
    const float* fln_g   = (const float*)d_in[20];
    const float* fln_b   = (const float*)d_in[21];
    const float* fmln_g  = (const float*)d_in[22];
    const float* fmln_b  = (const float*)d_in[23];
    float* out = (float*)d_out;

    float *q_, *k_, *v_, *attn_, *proj_, *x1_, *ff_, *sc_;
    __nv_bfloat16 *hh, *hl, *ah, *al, *fh, *fl;
    __nv_bfloat16 *wqh, *wql, *wkh, *wkl, *wvh, *wvl, *woh, *wol, *w1h, *w1l, *w2h, *w2l;
    cudaGetSymbolAddress((void**)&q_,    g_q);
    cudaGetSymbolAddress((void**)&k_,    g_k);
    cudaGetSymbolAddress((void**)&v_,    g_v);
    cudaGetSymbolAddress((void**)&attn_, g_attn);
    cudaGetSymbolAddress((void**)&proj_, g_proj);
    cudaGetSymbolAddress((void**)&x1_,   g_x1);
    cudaGetSymbolAddress((void**)&ff_,   g_ff);
    cudaGetSymbolAddress((void**)&sc_,   g_sc);
    cudaGetSymbolAddress((void**)&hh, g_hh);   cudaGetSymbolAddress((void**)&hl, g_hl);
    cudaGetSymbolAddress((void**)&ah, g_ah);   cudaGetSymbolAddress((void**)&al, g_al);
    cudaGetSymbolAddress((void**)&fh, g_fh);   cudaGetSymbolAddress((void**)&fl, g_fl);
    cudaGetSymbolAddress((void**)&wqh, g_wqh); cudaGetSymbolAddress((void**)&wql, g_wql);
    cudaGetSymbolAddress((void**)&wkh, g_wkh); cudaGetSymbolAddress((void**)&wkl, g_wkl);
    cudaGetSymbolAddress((void**)&wvh, g_wvh); cudaGetSymbolAddress((void**)&wvl, g_wvl);
    cudaGetSymbolAddress((void**)&woh, g_woh); cudaGetSymbolAddress((void**)&wol, g_wol);
    cudaGetSymbolAddress((void**)&w1h, g_w1h); cudaGetSymbolAddress((void**)&w1l, g_w1l);
    cudaGetSymbolAddress((void**)&w2h, g_w2h); cudaGetSymbolAddress((void**)&w2l, g_w2l);

    cudaFuncSetAttribute(hmma_gemm<EPI_BIAS>, cudaFuncAttributeMaxDynamicSharedMemorySize, GEMM_SMEM);
    cudaFuncSetAttribute(hmma_gemm<EPI_GELU>, cudaFuncAttributeMaxDynamicSharedMemorySize, GEMM_SMEM);
    cudaFuncSetAttribute(hmma_gemm<EPI_RES>,  cudaFuncAttributeMaxDynamicSharedMemorySize, GEMM_SMEM);

    // weight splits (every call; deterministic)
    const int nCC = Ct * Ct / 4, nFC = FFt * Ct / 4;
    split_bf16_kernel<<<nCC / 256, 256>>>(Wq, wqh, wql, nCC);
    split_bf16_kernel<<<nCC / 256, 256>>>(Wk, wkh, wkl, nCC);
    split_bf16_kernel<<<nCC / 256, 256>>>(Wv, wvh, wvl, nCC);
    split_bf16_kernel<<<nCC / 256, 256>>>(Wo, woh, wol, nCC);
    split_bf16_kernel<<<nFC / 256, 256>>>(W1, w1h, w1l, nFC);
    split_bf16_kernel<<<nFC / 256, 256>>>(W2, w2h, w2l, nFC);

    // ---- attention block ----
    ln_bf16_kernel<<<NTOK, 256>>>(x, ln_g, ln_b, hh, hl, Ct);

    dim3 gq(Ct / 128, NTOK / 128);   // (8, 32)
    hmma_gemm<EPI_BIAS><<<gq, 256, GEMM_SMEM>>>(hh, hl, wqh, wql, bq, nullptr, q_, Ct, Ct);
    hmma_gemm<EPI_BIAS><<<gq, 256, GEMM_SMEM>>>(hh, hl, wkh, wkl, bk, nullptr, k_, Ct, Ct);
    hmma_gemm<EPI_BIAS><<<gq, 256, GEMM_SMEM>>>(hh, hl, wvh, wvl, bv, nullptr, v_, Ct, Ct);

    dim3 gs(Lt / 128, Lt / 128, Bb * Ht);
    attn_scores_kernel<<<gs, 256>>>(q_, k_, ab, amask, sc_);
    softmax_kernel<<<Bb * Ht * Lt, 256>>>(sc_);
    dim3 gp(Lt / 64, Bb * Ht);
    attn_pv_kernel<<<gp, 256>>>(sc_, v_, c_attn, attn_);

    const int nAct = NTOK * Ct / 4;
    split_bf16_kernel<<<nAct / 256, 256>>>(attn_, ah, al, nAct);
    hmma_gemm<EPI_BIAS><<<gq, 256, GEMM_SMEM>>>(ah, al, woh, wol, bo, nullptr, proj_, Ct, Ct);
    ln_kernel<true><<<NTOK, 256>>>(proj_, mln_g, mln_b, x, x1_, Ct);

    // ---- FFN block ----
    ln_bf16_kernel<<<NTOK, 256>>>(x1_, fln_g, fln_b, hh, hl, Ct);

    dim3 g1(FFt / 128, NTOK / 128);  // (32, 32)
    hmma_gemm<EPI_GELU><<<g1, 256, GEMM_SMEM>>>(hh, hl, w1h, w1l, b1, nullptr, ff_, FFt, Ct);

    ln_bf16_kernel<<<NTOK, 256>>>(ff_, fmln_g, fmln_b, fh, fl, FFt);

    hmma_gemm<EPI_RES><<<gq, 256, GEMM_SMEM>>>(fh, fl, w2h, w2l, b2, x1_, out, Ct, FFt);
}

// round 5
// speedup vs baseline: 1.0011x; 1.0011x over previous
#include <cuda_runtime.h>
#include <cuda_bf16.h>
#include <math.h>
#include <stdint.h>

// Problem constants
#define Bb   4
#define Lt   1024
#define Ct   1024
#define Ht   16
#define Dt   64
#define FFt  4096
#define NTOK (Bb * Lt)
#define SCALE 0.08838834764831843f

// ---------------- scratch (static device allocations; allowed) ----------------
static __device__ float g_q   [(size_t)NTOK * Ct];
static __device__ float g_k   [(size_t)NTOK * Ct];
static __device__ float g_v   [(size_t)NTOK * Ct];
static __device__ float g_attn[(size_t)NTOK * Ct];
static __device__ float g_proj[(size_t)NTOK * Ct];
static __device__ float g_x1  [(size_t)NTOK * Ct];
static __device__ float g_ff  [(size_t)NTOK * FFt];
static __device__ float g_sc  [(size_t)Bb * Ht * Lt * Lt];

// split-bf16 activations (aligned for 16B cp.async)
static __device__ __align__(256) __nv_bfloat16 g_hh[(size_t)NTOK * Ct],  g_hl[(size_t)NTOK * Ct];
static __device__ __align__(256) __nv_bfloat16 g_ah[(size_t)NTOK * Ct],  g_al[(size_t)NTOK * Ct];
static __device__ __align__(256) __nv_bfloat16 g_fh[(size_t)NTOK * FFt], g_fl[(size_t)NTOK * FFt];
// split-bf16 weights
static __device__ __align__(256) __nv_bfloat16 g_wqh[(size_t)Ct * Ct],  g_wql[(size_t)Ct * Ct];
static __device__ __align__(256) __nv_bfloat16 g_wkh[(size_t)Ct * Ct],  g_wkl[(size_t)Ct * Ct];
static __device__ __align__(256) __nv_bfloat16 g_wvh[(size_t)Ct * Ct],  g_wvl[(size_t)Ct * Ct];
static __device__ __align__(256) __nv_bfloat16 g_woh[(size_t)Ct * Ct],  g_wol[(size_t)Ct * Ct];
static __device__ __align__(256) __nv_bfloat16 g_w1h[(size_t)FFt * Ct], g_w1l[(size_t)FFt * Ct];
static __device__ __align__(256) __nv_bfloat16 g_w2h[(size_t)Ct * FFt], g_w2l[(size_t)Ct * FFt];

__device__ __forceinline__ float gelu_exact(float x) {
    return 0.5f * x * (1.0f + erff(x * 0.70710678118654752f));
}

__device__ __forceinline__ uint32_t smem_u32(const void* p) {
    uint32_t a;
    asm("{ .reg .u64 t; cvta.to.shared.u64 t, %1; cvt.u32.u64 %0, t; }" : "=r"(a) : "l"(p));
    return a;
}

// ---------------- HMMA GEMM building blocks (base sm_103 features only) -------
#define LDMX4(d0, d1, d2, d3, addr) \
    asm volatile("ldmatrix.sync.aligned.m8n8.x4.shared.b16 {%0,%1,%2,%3}, [%4];" \
                 : "=r"(d0), "=r"(d1), "=r"(d2), "=r"(d3) : "r"(addr))

#define MMA16816(d, a, b) \
    asm volatile("mma.sync.aligned.m16n8k16.row.col.f32.bf16.bf16.f32 " \
                 "{%0,%1,%2,%3}, {%4,%5,%6,%7}, {%8,%9}, {%0,%1,%2,%3};" \
                 : "+f"((d)[0]), "+f"((d)[1]), "+f"((d)[2]), "+f"((d)[3]) \
                 : "r"((a)[0]), "r"((a)[1]), "r"((a)[2]), "r"((a)[3]), \
                   "r"((b)[0]), "r"((b)[1]))

#define CPASYNC16(saddr, gptr) \
    asm volatile("cp.async.cg.shared.global [%0], [%1], 16;" :: "r"(saddr), "l"(gptr))
#define CPCOMMIT() asm volatile("cp.async.commit_group;")
#define CPWAIT1()  asm volatile("cp.async.wait_group 1;")
#define CPWAIT0()  asm volatile("cp.async.wait_group 0;")

// 128 rows x 32 cols bf16 matrix in smem: 64B rows split into 4x16B segs,
// seg' = s ^ ((r>>1)&3)  -> conflict-free ldmatrix & stores.
__device__ __forceinline__ uint32_t swz(int r, int s) {
    return (uint32_t)(r * 64 + ((s ^ ((r >> 1) & 3)) << 4));
}

// stage layout: Ah @0, Al @8192, Bh @16384, Bl @24576 ; stage = 32768 B
#define STAGE 32768
#define GEMM_SMEM (2 * STAGE)

enum { EPI_BIAS = 0, EPI_GELU = 1, EPI_RES = 2 };

template <int EPI>
__global__ __launch_bounds__(256) void hmma_gemm(
    const __nv_bfloat16* __restrict__ Ah, const __nv_bfloat16* __restrict__ Al,
    const __nv_bfloat16* __restrict__ Bh, const __nv_bfloat16* __restrict__ Bl,
    const float* __restrict__ bias, const float* __restrict__ res,
    float* __restrict__ C, int N, int K)
{
    extern __shared__ __align__(128) char smem[];
    const uint32_t sb = smem_u32(smem);
    const int tid  = threadIdx.x;
    const int lane = tid & 31;
    const int wid  = tid >> 5;
    const int wm   = (wid & 1) * 64;     // warp m-offset (2 warps over M)
    const int wn   = (wid >> 1) * 32;    // warp n-offset (4 warps over N)

    const __nv_bfloat16* gAh = Ah + (size_t)blockIdx.y * 128 * K;
    const __nv_bfloat16* gAl = Al + (size_t)blockIdx.y * 128 * K;
    const __nv_bfloat16* gBh = Bh + (size_t)blockIdx.x * 128 * K;
    const __nv_bfloat16* gBl = Bl + (size_t)blockIdx.x * 128 * K;

    const int nch = K >> 5;

    // per-thread global/smem load mapping: 2 segs of 16B per matrix per chunk
    const int r0 = tid >> 2,          s0 = tid & 3;
    const int r1 = (tid + 256) >> 2;  // s1 == s0
    const uint32_t sw0 = swz(r0, s0);
    const uint32_t sw1 = swz(r1, s0);
    const size_t go0 = (size_t)r0 * K + s0 * 8;
    const size_t go1 = (size_t)r1 * K + s0 * 8;

#define ISSUE(c)                                                              \
    do {                                                                      \
        const uint32_t bs_ = sb + ((c) & 1) * STAGE;                          \
        const size_t kof_ = (size_t)(c) * 32;                                 \
        CPASYNC16(bs_ + 0     + sw0, gAh + go0 + kof_);                       \
        CPASYNC16(bs_ + 0     + sw1, gAh + go1 + kof_);                       \
        CPASYNC16(bs_ + 8192  + sw0, gAl + go0 + kof_);                       \
        CPASYNC16(bs_ + 8192  + sw1, gAl + go1 + kof_);                       \
        CPASYNC16(bs_ + 16384 + sw0, gBh + go0 + kof_);                       \
        CPASYNC16(bs_ + 16384 + sw1, gBh + go1 + kof_);                       \
        CPASYNC16(bs_ + 24576 + sw0, gBl + go0 + kof_);                       \
        CPASYNC16(bs_ + 24576 + sw1, gBl + go1 + kof_);                       \
        CPCOMMIT();                                                           \
    } while (0)

    ISSUE(0);
    ISSUE(1);

    float acc[4][4][4];
#pragma unroll
    for (int i = 0; i < 4; i++)
#pragma unroll
        for (int j = 0; j < 4; j++)
#pragma unroll
            for (int t = 0; t < 4; t++) acc[i][j][t] = 0.0f;

    for (int c = 0; c < nch; c++) {
        if (c < nch - 1) CPWAIT1(); else CPWAIT0();
        __syncthreads();
        const uint32_t base = sb + (c & 1) * STAGE;

#pragma unroll
        for (int ks = 0; ks < 2; ks++) {
            uint32_t ah[4][4], al_[4][4], bh[4][2], bl_[4][2];
            const int ar  = wm + (lane & 15);
            const int as_ = ks * 2 + (lane >> 4);
#pragma unroll
            for (int mi = 0; mi < 4; mi++) {
                uint32_t ad = base + swz(ar + mi * 16, as_);
                LDMX4(ah[mi][0], ah[mi][1], ah[mi][2], ah[mi][3], ad);
                uint32_t ad2 = base + 8192 + swz(ar + mi * 16, as_);
                LDMX4(al_[mi][0], al_[mi][1], al_[mi][2], al_[mi][3], ad2);
            }
            const int br = wn + ((lane >> 4) & 1) * 8 + (lane & 7);
            const int bs2 = ks * 2 + ((lane >> 3) & 1);
#pragma unroll
            for (int np = 0; np < 2; np++) {
                uint32_t bd = base + 16384 + swz(br + np * 16, bs2);
                LDMX4(bh[np * 2][0], bh[np * 2][1], bh[np * 2 + 1][0], bh[np * 2 + 1][1], bd);
                uint32_t bd2 = base + 24576 + swz(br + np * 16, bs2);
                LDMX4(bl_[np * 2][0], bl_[np * 2][1], bl_[np * 2 + 1][0], bl_[np * 2 + 1][1], bd2);
            }
#pragma unroll
            for (int mi = 0; mi < 4; mi++)
#pragma unroll
                for (int nt = 0; nt < 4; nt++) MMA16816(acc[mi][nt], ah[mi], bh[nt]);
#pragma unroll
            for (int mi = 0; mi < 4; mi++)
#pragma unroll
                for (int nt = 0; nt < 4; nt++) MMA16816(acc[mi][nt], ah[mi], bl_[nt]);
#pragma unroll
            for (int mi = 0; mi < 4; mi++)
#pragma unroll
                for (int nt = 0; nt < 4; nt++) MMA16816(acc[mi][nt], al_[mi], bh[nt]);
        }

        __syncthreads();
        if (c + 2 < nch) ISSUE(c + 2);
    }
#undef ISSUE

    // epilogue
    const int rbase = blockIdx.y * 128 + wm + (lane >> 2);
    const int cbase = blockIdx.x * 128 + wn + (lane & 3) * 2;
#pragma unroll
    for (int mi = 0; mi < 4; mi++) {
#pragma unroll
        for (int half = 0; half < 2; half++) {
            const int row = rbase + mi * 16 + half * 8;
            const size_t ro = (size_t)row * N;
#pragma unroll
            for (int nt = 0; nt < 4; nt++) {
                const int col = cbase + nt * 8;
                float v0 = acc[mi][nt][half * 2 + 0] + bias[col];
                float v1 = acc[mi][nt][half * 2 + 1] + bias[col + 1];
                if (EPI == EPI_GELU) { v0 = gelu_exact(v0); v1 = gelu_exact(v1); }
                if (EPI == EPI_RES)  { v0 += res[ro + col]; v1 += res[ro + col + 1]; }
                C[ro + col]     = v0;
                C[ro + col + 1] = v1;
            }
        }
    }
}

// ---------------- fp32 -> split bf16 (hi/lo) ----------------
__global__ __launch_bounds__(256) void split_bf16_kernel(
    const float* __restrict__ s, __nv_bfloat16* __restrict__ hi,
    __nv_bfloat16* __restrict__ lo, int n4)
{
    int i = blockIdx.x * 256 + threadIdx.x;
    if (i >= n4) return;
    float4 v = ((const float4*)s)[i];
    float vv[4] = {v.x, v.y, v.z, v.w};
#pragma unroll
    for (int k = 0; k < 4; k++) {
        __nv_bfloat16 h = __float2bfloat16(vv[k]);
        __nv_bfloat16 l = __float2bfloat16(vv[k] - __bfloat162float(h));
        hi[(size_t)i * 4 + k] = h;
        lo[(size_t)i * 4 + k] = l;
    }
}

// ---------------- layernorm -> split bf16 ----------------
__global__ __launch_bounds__(256) void ln_bf16_kernel(
    const float* __restrict__ in, const float* __restrict__ g, const float* __restrict__ be,
    __nv_bfloat16* __restrict__ hi, __nv_bfloat16* __restrict__ lo, int cols)
{
    const size_t base = (size_t)blockIdx.x * cols;
    const int tid = threadIdx.x;
    __shared__ float rs[32], rs2[32];

    float s = 0.0f, s2 = 0.0f;
    for (int c = tid; c < cols; c += 256) {
        float x = in[base + c];
        s += x; s2 += x * x;
    }
#pragma unroll
    for (int o = 16; o; o >>= 1) {
        s  += __shfl_xor_sync(0xffffffffu, s,  o);
        s2 += __shfl_xor_sync(0xffffffffu, s2, o);
    }
    if ((tid & 31) == 0) { rs[tid >> 5] = s; rs2[tid >> 5] = s2; }
    __syncthreads();
    if (tid == 0) {
        float a = 0.0f, a2 = 0.0f;
        for (int i = 0; i < 8; i++) { a += rs[i]; a2 += rs2[i]; }
        rs[0] = a; rs2[0] = a2;
    }
    __syncthreads();
    const float icols = 1.0f / (float)cols;
    const float mean = rs[0] * icols;
    const float var  = rs2[0] * icols - mean * mean;
    const float rstd = rsqrtf(var + 1e-5f);

    for (int c = tid; c < cols; c += 256) {
        float x = in[base + c];
        float val = (x - mean) * rstd * g[c] + be[c];
        __nv_bfloat16 h = __float2bfloat16(val);
        hi[base + c] = h;
        lo[base + c] = __float2bfloat16(val - __bfloat162float(h));
    }
}

// ---------------- layernorm fp32 (+residual) ----------------
template <bool RES>
__global__ __launch_bounds__(256) void ln_kernel(
    const float* __restrict__ in, const float* __restrict__ g, const float* __restrict__ be,
    const float* __restrict__ res, float* __restrict__ out, int cols)
{
    const size_t base = (size_t)blockIdx.x * cols;
    const int tid = threadIdx.x;
    __shared__ float rs[32], rs2[32];

    float s = 0.0f, s2 = 0.0f;
    for (int c = tid; c < cols; c += 256) {
        float x = in[base + c];
        s += x; s2 += x * x;
    }
#pragma unroll
    for (int o = 16; o; o >>= 1) {
        s  += __shfl_xor_sync(0xffffffffu, s,  o);
        s2 += __shfl_xor_sync(0xffffffffu, s2, o);
    }
    if ((tid & 31) == 0) { rs[tid >> 5] = s; rs2[tid >> 5] = s2; }
    __syncthreads();
    if (tid == 0) {
        float a = 0.0f, a2 = 0.0f;
        for (int i = 0; i < 8; i++) { a += rs[i]; a2 += rs2[i]; }
        rs[0] = a; rs2[0] = a2;
    }
    __syncthreads();
    const float icols = 1.0f / (float)cols;
    const float mean = rs[0] * icols;
    const float var  = rs2[0] * icols - mean * mean;
    const float rstd = rsqrtf(var + 1e-5f);

    for (int c = tid; c < cols; c += 256) {
        float x = in[base + c];
        float val = (x - mean) * rstd * g[c] + be[c];
        if (RES) val += res[base + c];
        out[base + c] = val;
    }
}

// ---------------- attention scores: S = scale*Q@K^T + bias + mask ----------------
__global__ __launch_bounds__(256) void attn_scores_kernel(
    const float* __restrict__ q, const float* __restrict__ k,
    const float* __restrict__ bias, const float* __restrict__ mask,
    float* __restrict__ S)
{
    __shared__ float As[8][128];
    __shared__ float Bs[8][128];
    const int tid  = threadIdx.x;
    const int tx   = tid & 15;
    const int ty   = tid >> 4;
    const int lRow = tid >> 1;
    const int lCol = (tid & 1) << 2;

    const int bh = blockIdx.z;
    const int b  = bh >> 4;
    const int h  = bh & 15;

    const float* Ab  = q + (size_t)b * Lt * Ct + h * Dt + (size_t)blockIdx.y * 128 * Ct;
    const float* Bbp = k + (size_t)b * Lt * Ct + h * Dt + (size_t)blockIdx.x * 128 * Ct;

    float acc[8][8];
#pragma unroll
    for (int i = 0; i < 8; i++)
#pragma unroll
        for (int j = 0; j < 8; j++) acc[i][j] = 0.0f;

    for (int k0 = 0; k0 < Dt; k0 += 8) {
        float4 a4 = *reinterpret_cast<const float4*>(Ab  + (size_t)lRow * Ct + k0 + lCol);
        float4 b4 = *reinterpret_cast<const float4*>(Bbp + (size_t)lRow * Ct + k0 + lCol);
        __syncthreads();
        As[lCol + 0][lRow] = a4.x; As[lCol + 1][lRow] = a4.y;
        As[lCol + 2][lRow] = a4.z; As[lCol + 3][lRow] = a4.w;
        Bs[lCol + 0][lRow] = b4.x; Bs[lCol + 1][lRow] = b4.y;
        Bs[lCol + 2][lRow] = b4.z; Bs[lCol + 3][lRow] = b4.w;
        __syncthreads();
#pragma unroll
        for (int kk = 0; kk < 8; kk++) {
            float4 a0 = *reinterpret_cast<const float4*>(&As[kk][ty * 8]);
            float4 a1 = *reinterpret_cast<const float4*>(&As[kk][ty * 8 + 4]);
            float4 b0 = *reinterpret_cast<const float4*>(&Bs[kk][tx * 8]);
            float4 b1 = *reinterpret_cast<const float4*>(&Bs[kk][tx * 8 + 4]);
            float a[8] = {a0.x, a0.y, a0.z, a0.w, a1.x, a1.y, a1.z, a1.w};
            float bv[8] = {b0.x, b0.y, b0.z, b0.w, b1.x, b1.y, b1.z, b1.w};
#pragma unroll
            for (int i = 0; i < 8; i++)
#pragma unroll
                for (int j = 0; j < 8; j++) acc[i][j] = fmaf(a[i], bv[j], acc[i][j]);
        }
    }

    const size_t sbs = (size_t)bh * Lt * Lt;
    const size_t mb  = (size_t)b * Lt * Lt;
    const int row0 = blockIdx.y * 128 + ty * 8;
    const int col0 = blockIdx.x * 128 + tx * 8;
#pragma unroll
    for (int i = 0; i < 8; i++) {
        size_t ro = (size_t)(row0 + i) * Lt + col0;
#pragma unroll
        for (int j = 0; j < 8; j++)
            S[sbs + ro + j] = acc[i][j] * SCALE + bias[sbs + ro + j] + mask[mb + ro + j];
    }
}

// ---------------- softmax over last dim (L=1024), in-place ----------------
__global__ __launch_bounds__(256) void softmax_kernel(float* __restrict__ S)
{
    const size_t base = (size_t)blockIdx.x * Lt;
    const int tid = threadIdx.x;
    __shared__ float red[32];

    float v[4];
    float mx = -1e30f;
#pragma unroll
    for (int i = 0; i < 4; i++) { v[i] = S[base + tid + i * 256]; mx = fmaxf(mx, v[i]); }
#pragma unroll
    for (int o = 16; o; o >>= 1) mx = fmaxf(mx, __shfl_xor_sync(0xffffffffu, mx, o));
    if ((tid & 31) == 0) red[tid >> 5] = mx;
    __syncthreads();
    if (tid == 0) {
        float m = red[0];
        for (int i = 1; i < 8; i++) m = fmaxf(m, red[i]);
        red[0] = m;
    }
    __syncthreads();
    mx = red[0];

    float s = 0.0f;
#pragma unroll
    for (int i = 0; i < 4; i++) { v[i] = __expf(v[i] - mx); s += v[i]; }
#pragma unroll
    for (int o = 16; o; o >>= 1) s += __shfl_xor_sync(0xffffffffu, s, o);
    __syncthreads();
    if ((tid & 31) == 0) red[tid >> 5] = s;
    __syncthreads();
    if (tid == 0) {
        float t = 0.0f;
        for (int i = 0; i < 8; i++) t += red[i];
        red[0] = t;
    }
    __syncthreads();
    const float inv = 1.0f / red[0];
#pragma unroll
    for (int i = 0; i < 4; i++) S[base + tid + i * 256] = v[i] * inv;
}

// ---------------- attn output: O = P @ V_head, scaled by c_attn[h] -------------
__global__ __launch_bounds__(256) void attn_pv_kernel(
    const float* __restrict__ S, const float* __restrict__ v,
    const float* __restrict__ c_attn, float* __restrict__ out)
{
    __shared__ float Ps[16][64];
    __shared__ float Vs[16][68];
    const int tid = threadIdx.x;
    const int tx = tid & 15;
    const int ty = tid >> 4;
    const int pRow = tid >> 2;
    const int pCol = (tid & 3) << 2;
    const int vRow = tid >> 4;
    const int vCol = (tid & 15) << 2;

    const int bh = blockIdx.y;
    const int b  = bh >> 4;
    const int h  = bh & 15;

    const float* Pb = S + (size_t)bh * Lt * Lt + (size_t)blockIdx.x * 64 * Lt;
    const float* Vb = v + (size_t)b * Lt * Ct + h * Dt;

    float acc[4][4];
#pragma unroll
    for (int i = 0; i < 4; i++)
#pragma unroll
        for (int j = 0; j < 4; j++) acc[i][j] = 0.0f;

    for (int k0 = 0; k0 < Lt; k0 += 16) {
        float4 p4 = *reinterpret_cast<const float4*>(Pb + (size_t)pRow * Lt + k0 + pCol);
        float4 v4 = *reinterpret_cast<const float4*>(Vb + (size_t)(k0 + vRow) * Ct + vCol);
        __syncthreads();
        Ps[pCol + 0][pRow] = p4.x; Ps[pCol + 1][pRow] = p4.y;
        Ps[pCol + 2][pRow] = p4.z; Ps[pCol + 3][pRow] = p4.w;
        Vs[vRow][vCol + 0] = v4.x; Vs[vRow][vCol + 1] = v4.y;
        Vs[vRow][vCol + 2] = v4.z; Vs[vRow][vCol + 3] = v4.w;
        __syncthreads();
#pragma unroll
        for (int kk = 0; kk < 16; kk++) {
            float a[4] = {Ps[kk][ty * 4 + 0], Ps[kk][ty * 4 + 1],
                          Ps[kk][ty * 4 + 2], Ps[kk][ty * 4 + 3]};
            float bvv[4] = {Vs[kk][tx * 4 + 0], Vs[kk][tx * 4 + 1],
                            Vs[kk][tx * 4 + 2], Vs[kk][tx * 4 + 3]};
#pragma unroll
            for (int i = 0; i < 4; i++)
#pragma unroll
                for (int j = 0; j < 4; j++) acc[i][j] = fmaf(a[i], bvv[j], acc[i][j]);
        }
    }

    const float cs = c_attn[h];
    const int row0 = blockIdx.x * 64 + ty * 4;
    const int col0 = tx * 4;
#pragma unroll
    for (int i = 0; i < 4; i++)
#pragma unroll
        for (int j = 0; j < 4; j++)
            out[((size_t)b * Lt + row0 + i) * Ct + h * Dt + col0 + j] = acc[i][j] * cs;
}

// ---------------- launch ----------------
extern "C" void kernel_launch(void* const* d_in, const int* in_sizes, int n_in,
                              void* d_out, int out_size)
{
    const float* x       = (const float*)d_in[0];
    const float* ab      = (const float*)d_in[1];
    const float* amask   = (const float*)d_in[2];
    const float* Wq      = (const float*)d_in[3];
    const float* bq      = (const float*)d_in[4];
    const float* Wk      = (const float*)d_in[5];
    const float* bk      = (const float*)d_in[6];
    const float* Wv      = (const float*)d_in[7];
    const float* bv      = (const float*)d_in[8];
    const float* Wo      = (const float*)d_in[9];
    const float* bo      = (const float*)d_in[10];
    const float* c_attn  = (const float*)d_in[11];
    const float* W1      = (const float*)d_in[12];
    const float* b1      = (const float*)d_in[13];
    const float* W2      = (const float*)d_in[14];
    const float* b2      = (const float*)d_in[15];
    const float* ln_g    = (const float*)d_in[16];
    const float* ln_b    = (const float*)d_in[17];
    const float* mln_g   = (const float*)d_in[18];
    const float* mln_b   = (const float*)d_in[19];
    const float* fln_g   = (const float*)d_in[20];
    const float* fln_b   = (const float*)d_in[21];
    const float* fmln_g  = (const float*)d_in[22];
    const float* fmln_b  = (const float*)d_in[23];
    float* out = (float*)d_out;

    float *q_, *k_, *v_, *attn_, *proj_, *x1_, *ff_, *sc_;
    __nv_bfloat16 *hh, *hl, *ah, *al, *fh, *fl;
    __nv_bfloat16 *wqh, *wql, *wkh, *wkl, *wvh, *wvl, *woh, *wol, *w1h, *w1l, *w2h, *w2l;
    cudaGetSymbolAddress((void**)&q_,    g_q);
    cudaGetSymbolAddress((void**)&k_,    g_k);
    cudaGetSymbolAddress((void**)&v_,    g_v);
    cudaGetSymbolAddress((void**)&attn_, g_attn);
    cudaGetSymbolAddress((void**)&proj_, g_proj);
    cudaGetSymbolAddress((void**)&x1_,   g_x1);
    cudaGetSymbolAddress((void**)&ff_,   g_ff);
    cudaGetSymbolAddress((void**)&sc_,   g_sc);
    cudaGetSymbolAddress((void**)&hh, g_hh);   cudaGetSymbolAddress((void**)&hl, g_hl);
    cudaGetSymbolAddress((void**)&ah, g_ah);   cudaGetSymbolAddress((void**)&al, g_al);
    cudaGetSymbolAddress((void**)&fh, g_fh);   cudaGetSymbolAddress((void**)&fl, g_fl);
    cudaGetSymbolAddress((void**)&wqh, g_wqh); cudaGetSymbolAddress((void**)&wql, g_wql);
    cudaGetSymbolAddress((void**)&wkh, g_wkh); cudaGetSymbolAddress((void**)&wkl, g_wkl);
    cudaGetSymbolAddress((void**)&wvh, g_wvh); cudaGetSymbolAddress((void**)&wvl, g_wvl);
    cudaGetSymbolAddress((void**)&woh, g_woh); cudaGetSymbolAddress((void**)&wol, g_wol);
    cudaGetSymbolAddress((void**)&w1h, g_w1h); cudaGetSymbolAddress((void**)&w1l, g_w1l);
    cudaGetSymbolAddress((void**)&w2h, g_w2h); cudaGetSymbolAddress((void**)&w2l, g_w2l);

    cudaFuncSetAttribute(hmma_gemm<EPI_BIAS>, cudaFuncAttributeMaxDynamicSharedMemorySize, GEMM_SMEM);
    cudaFuncSetAttribute(hmma_gemm<EPI_GELU>, cudaFuncAttributeMaxDynamicSharedMemorySize, GEMM_SMEM);
    cudaFuncSetAttribute(hmma_gemm<EPI_RES>,  cudaFuncAttributeMaxDynamicSharedMemorySize, GEMM_SMEM);

    // weight splits (every call; deterministic)
    const int nCC = Ct * Ct / 4, nFC = FFt * Ct / 4;
    split_bf16_kernel<<<nCC / 256, 256>>>(Wq, wqh, wql, nCC);
    split_bf16_kernel<<<nCC / 256, 256>>>(Wk, wkh, wkl, nCC);
    split_bf16_kernel<<<nCC / 256, 256>>>(Wv, wvh, wvl, nCC);
    split_bf16_kernel<<<nCC / 256, 256>>>(Wo, woh, wol, nCC);
    split_bf16_kernel<<<nFC / 256, 256>>>(W1, w1h, w1l, nFC);
    split_bf16_kernel<<<nFC / 256, 256>>>(W2, w2h, w2l, nFC);

    // ---- attention block ----
    ln_bf16_kernel<<<NTOK, 256>>>(x, ln_g, ln_b, hh, hl, Ct);

    dim3 gq(Ct / 128, NTOK / 128);   // (8, 32)
    hmma_gemm<EPI_BIAS><<<gq, 256, GEMM_SMEM>>>(hh, hl, wqh, wql, bq, nullptr, q_, Ct, Ct);
    hmma_gemm<EPI_BIAS><<<gq, 256, GEMM_SMEM>>>(hh, hl, wkh, wkl, bk, nullptr, k_, Ct, Ct);
    hmma_gemm<EPI_BIAS><<<gq, 256, GEMM_SMEM>>>(hh, hl, wvh, wvl, bv, nullptr, v_, Ct, Ct);

    dim3 gs(Lt / 128, Lt / 128, Bb * Ht);
    attn_scores_kernel<<<gs, 256>>>(q_, k_, ab, amask, sc_);
    softmax_kernel<<<Bb * Ht * Lt, 256>>>(sc_);
    dim3 gp(Lt / 64, Bb * Ht);
    attn_pv_kernel<<<gp, 256>>>(sc_, v_, c_attn, attn_);

    const int nAct = NTOK * Ct / 4;
    split_bf16_kernel<<<nAct / 256, 256>>>(attn_, ah, al, nAct);
    hmma_gemm<EPI_BIAS><<<gq, 256, GEMM_SMEM>>>(ah, al, woh, wol, bo, nullptr, proj_, Ct, Ct);
    ln_kernel<true><<<NTOK, 256>>>(proj_, mln_g, mln_b, x, x1_, Ct);

    // ---- FFN block ----
    ln_bf16_kernel<<<NTOK, 256>>>(x1_, fln_g, fln_b, hh, hl, Ct);

    dim3 g1(FFt / 128, NTOK / 128);  // (32, 32)
    hmma_gemm<EPI_GELU><<<g1, 256, GEMM_SMEM>>>(hh, hl, w1h, w1l, b1, nullptr, ff_, FFt, Ct);

    ln_bf16_kernel<<<NTOK, 256>>>(ff_, fmln_g, fmln_b, fh, fl, FFt);

    hmma_gemm<EPI_RES><<<gq, 256, GEMM_SMEM>>>(fh, fl, w2h, w2l, b2, x1_, out, Ct, FFt);
}

// round 6
// speedup vs baseline: 1.4887x; 1.4871x over previous
#include <cuda_runtime.h>
#include <cuda_bf16.h>
#include <math.h>
#include <stdint.h>

// Problem constants
#define Bb   4
#define Lt   1024
#define Ct   1024
#define Ht   16
#define Dt   64
#define FFt  4096
#define NTOK (Bb * Lt)
#define SCALE 0.08838834764831843f

// ---------------- scratch (static device allocations; allowed) ----------------
static __device__ float g_proj[(size_t)NTOK * Ct];
static __device__ float g_x1  [(size_t)NTOK * Ct];
static __device__ float g_ff  [(size_t)NTOK * FFt];

// split-bf16 activations
static __device__ __align__(256) __nv_bfloat16 g_hh[(size_t)NTOK * Ct],  g_hl[(size_t)NTOK * Ct];
static __device__ __align__(256) __nv_bfloat16 g_qh[(size_t)NTOK * Ct],  g_ql[(size_t)NTOK * Ct];
static __device__ __align__(256) __nv_bfloat16 g_kh[(size_t)NTOK * Ct],  g_kl[(size_t)NTOK * Ct];
static __device__ __align__(256) __nv_bfloat16 g_vh[(size_t)NTOK * Ct],  g_vl[(size_t)NTOK * Ct];
static __device__ __align__(256) __nv_bfloat16 g_oh[(size_t)NTOK * Ct],  g_ol[(size_t)NTOK * Ct];
static __device__ __align__(256) __nv_bfloat16 g_fh[(size_t)NTOK * FFt], g_fl[(size_t)NTOK * FFt];
// split-bf16 weights
static __device__ __align__(256) __nv_bfloat16 g_wqh[(size_t)Ct * Ct],  g_wql[(size_t)Ct * Ct];
static __device__ __align__(256) __nv_bfloat16 g_wkh[(size_t)Ct * Ct],  g_wkl[(size_t)Ct * Ct];
static __device__ __align__(256) __nv_bfloat16 g_wvh[(size_t)Ct * Ct],  g_wvl[(size_t)Ct * Ct];
static __device__ __align__(256) __nv_bfloat16 g_woh[(size_t)Ct * Ct],  g_wol[(size_t)Ct * Ct];
static __device__ __align__(256) __nv_bfloat16 g_w1h[(size_t)FFt * Ct], g_w1l[(size_t)FFt * Ct];
static __device__ __align__(256) __nv_bfloat16 g_w2h[(size_t)Ct * FFt], g_w2l[(size_t)Ct * FFt];

__device__ __forceinline__ float gelu_exact(float x) {
    return 0.5f * x * (1.0f + erff(x * 0.70710678118654752f));
}

__device__ __forceinline__ uint32_t smem_u32(const void* p) {
    uint32_t a;
    asm("{ .reg .u64 t; cvta.to.shared.u64 t, %1; cvt.u32.u64 %0, t; }" : "=r"(a) : "l"(p));
    return a;
}

// ---------------- HMMA building blocks (base sm_103 features) -------
#define LDMX4(d0, d1, d2, d3, addr) \
    asm volatile("ldmatrix.sync.aligned.m8n8.x4.shared.b16 {%0,%1,%2,%3}, [%4];" \
                 : "=r"(d0), "=r"(d1), "=r"(d2), "=r"(d3) : "r"(addr))

#define LDMX4T(d0, d1, d2, d3, addr) \
    asm volatile("ldmatrix.sync.aligned.m8n8.x4.trans.shared.b16 {%0,%1,%2,%3}, [%4];" \
                 : "=r"(d0), "=r"(d1), "=r"(d2), "=r"(d3) : "r"(addr))

#define MMA16816(d, a, b) \
    asm volatile("mma.sync.aligned.m16n8k16.row.col.f32.bf16.bf16.f32 " \
                 "{%0,%1,%2,%3}, {%4,%5,%6,%7}, {%8,%9}, {%0,%1,%2,%3};" \
                 : "+f"((d)[0]), "+f"((d)[1]), "+f"((d)[2]), "+f"((d)[3]) \
                 : "r"((a)[0]), "r"((a)[1]), "r"((a)[2]), "r"((a)[3]), \
                   "r"((b)[0]), "r"((b)[1]))

#define CPASYNC16(saddr, gptr) \
    asm volatile("cp.async.cg.shared.global [%0], [%1], 16;" :: "r"(saddr), "l"(gptr))
#define CPCOMMIT() asm volatile("cp.async.commit_group;")
#define CPWAIT1()  asm volatile("cp.async.wait_group 1;")
#define CPWAIT0()  asm volatile("cp.async.wait_group 0;")

// GEMM smem: 128 rows x 32 cols bf16 (64B rows, 4x16B segs), seg' = s ^ ((r>>1)&3)
__device__ __forceinline__ uint32_t swz(int r, int s) {
    return (uint32_t)(r * 64 + ((s ^ ((r >> 1) & 3)) << 4));
}
// Flash smem: 128 rows x 64 cols bf16 (128B rows, 8x16B segs), seg' = s ^ (r&7)
__device__ __forceinline__ uint32_t off8(int r, int s) {
    return (uint32_t)(r * 128 + ((s ^ (r & 7)) << 4));
}

__device__ __forceinline__ uint32_t packbf2(float x, float y) {
    __nv_bfloat162 t = __floats2bfloat162_rn(x, y);
    return *(uint32_t*)&t;
}

// ============================ dense GEMM =====================================
#define STAGE 32768
#define GEMM_SMEM (2 * STAGE)

enum { EPI_BIAS = 0, EPI_GELU = 1, EPI_RES = 2, EPI_SPLIT = 3 };

template <int EPI>
__global__ __launch_bounds__(256) void hmma_gemm(
    const __nv_bfloat16* __restrict__ Ah, const __nv_bfloat16* __restrict__ Al,
    const __nv_bfloat16* __restrict__ Bh, const __nv_bfloat16* __restrict__ Bl,
    const float* __restrict__ bias, const float* __restrict__ res,
    float* __restrict__ C, __nv_bfloat16* __restrict__ Chi,
    __nv_bfloat16* __restrict__ Clo, int N, int K)
{
    extern __shared__ __align__(128) char smem[];
    const uint32_t sb = smem_u32(smem);
    const int tid  = threadIdx.x;
    const int lane = tid & 31;
    const int wid  = tid >> 5;
    const int wm   = (wid & 1) * 64;
    const int wn   = (wid >> 1) * 32;

    const __nv_bfloat16* gAh = Ah + (size_t)blockIdx.y * 128 * K;
    const __nv_bfloat16* gAl = Al + (size_t)blockIdx.y * 128 * K;
    const __nv_bfloat16* gBh = Bh + (size_t)blockIdx.x * 128 * K;
    const __nv_bfloat16* gBl = Bl + (size_t)blockIdx.x * 128 * K;

    const int nch = K >> 5;
    const int r0 = tid >> 2,          s0 = tid & 3;
    const int r1 = (tid + 256) >> 2;
    const uint32_t sw0 = swz(r0, s0);
    const uint32_t sw1 = swz(r1, s0);
    const size_t go0 = (size_t)r0 * K + s0 * 8;
    const size_t go1 = (size_t)r1 * K + s0 * 8;

#define ISSUE(c)                                                              \
    do {                                                                      \
        const uint32_t bs_ = sb + ((c) & 1) * STAGE;                          \
        const size_t kof_ = (size_t)(c) * 32;                                 \
        CPASYNC16(bs_ + 0     + sw0, gAh + go0 + kof_);                       \
        CPASYNC16(bs_ + 0     + sw1, gAh + go1 + kof_);                       \
        CPASYNC16(bs_ + 8192  + sw0, gAl + go0 + kof_);                       \
        CPASYNC16(bs_ + 8192  + sw1, gAl + go1 + kof_);                       \
        CPASYNC16(bs_ + 16384 + sw0, gBh + go0 + kof_);                       \
        CPASYNC16(bs_ + 16384 + sw1, gBh + go1 + kof_);                       \
        CPASYNC16(bs_ + 24576 + sw0, gBl + go0 + kof_);                       \
        CPASYNC16(bs_ + 24576 + sw1, gBl + go1 + kof_);                       \
        CPCOMMIT();                                                           \
    } while (0)

    ISSUE(0);
    ISSUE(1);

    float acc[4][4][4];
#pragma unroll
    for (int i = 0; i < 4; i++)
#pragma unroll
        for (int j = 0; j < 4; j++)
#pragma unroll
            for (int t = 0; t < 4; t++) acc[i][j][t] = 0.0f;

    for (int c = 0; c < nch; c++) {
        if (c < nch - 1) CPWAIT1(); else CPWAIT0();
        __syncthreads();
        const uint32_t base = sb + (c & 1) * STAGE;

#pragma unroll
        for (int ks = 0; ks < 2; ks++) {
            uint32_t ah[4][4], al_[4][4], bh[4][2], bl_[4][2];
            const int ar  = wm + (lane & 15);
            const int as_ = ks * 2 + (lane >> 4);
#pragma unroll
            for (int mi = 0; mi < 4; mi++) {
                uint32_t ad = base + swz(ar + mi * 16, as_);
                LDMX4(ah[mi][0], ah[mi][1], ah[mi][2], ah[mi][3], ad);
                uint32_t ad2 = base + 8192 + swz(ar + mi * 16, as_);
                LDMX4(al_[mi][0], al_[mi][1], al_[mi][2], al_[mi][3], ad2);
            }
            const int br = wn + ((lane >> 4) & 1) * 8 + (lane & 7);
            const int bs2 = ks * 2 + ((lane >> 3) & 1);
#pragma unroll
            for (int np = 0; np < 2; np++) {
                uint32_t bd = base + 16384 + swz(br + np * 16, bs2);
                LDMX4(bh[np * 2][0], bh[np * 2][1], bh[np * 2 + 1][0], bh[np * 2 + 1][1], bd);
                uint32_t bd2 = base + 24576 + swz(br + np * 16, bs2);
                LDMX4(bl_[np * 2][0], bl_[np * 2][1], bl_[np * 2 + 1][0], bl_[np * 2 + 1][1], bd2);
            }
#pragma unroll
            for (int mi = 0; mi < 4; mi++)
#pragma unroll
                for (int nt = 0; nt < 4; nt++) MMA16816(acc[mi][nt], ah[mi], bh[nt]);
#pragma unroll
            for (int mi = 0; mi < 4; mi++)
#pragma unroll
                for (int nt = 0; nt < 4; nt++) MMA16816(acc[mi][nt], ah[mi], bl_[nt]);
#pragma unroll
            for (int mi = 0; mi < 4; mi++)
#pragma unroll
                for (int nt = 0; nt < 4; nt++) MMA16816(acc[mi][nt], al_[mi], bh[nt]);
        }

        __syncthreads();
        if (c + 2 < nch) ISSUE(c + 2);
    }
#undef ISSUE

    const int rbase = blockIdx.y * 128 + wm + (lane >> 2);
    const int cbase = blockIdx.x * 128 + wn + (lane & 3) * 2;
#pragma unroll
    for (int mi = 0; mi < 4; mi++) {
#pragma unroll
        for (int half = 0; half < 2; half++) {
            const int row = rbase + mi * 16 + half * 8;
            const size_t ro = (size_t)row * N;
#pragma unroll
            for (int nt = 0; nt < 4; nt++) {
                const int col = cbase + nt * 8;
                float v0 = acc[mi][nt][half * 2 + 0] + bias[col];
                float v1 = acc[mi][nt][half * 2 + 1] + bias[col + 1];
                if (EPI == EPI_GELU) { v0 = gelu_exact(v0); v1 = gelu_exact(v1); }
                if (EPI == EPI_RES)  { v0 += res[ro + col]; v1 += res[ro + col + 1]; }
                if (EPI == EPI_SPLIT) {
                    __nv_bfloat162 h2 = __floats2bfloat162_rn(v0, v1);
                    *(__nv_bfloat162*)(Chi + ro + col) = h2;
                    *(__nv_bfloat162*)(Clo + ro + col) =
                        __floats2bfloat162_rn(v0 - __low2float(h2), v1 - __high2float(h2));
                } else {
                    C[ro + col]     = v0;
                    C[ro + col + 1] = v1;
                }
            }
        }
    }
}

// ============================ flash attention ================================
// CTA: 128 q-rows of one (b,h). smem: Qh@0 Ql@16K, stage s@32K+s*64K: Kh,Kl,Vh,Vl.
#define FA_SMEM (32768 + 2 * 65536)

__global__ __launch_bounds__(256, 1) void flash_attn(
    const __nv_bfloat16* __restrict__ qh, const __nv_bfloat16* __restrict__ ql,
    const __nv_bfloat16* __restrict__ kh, const __nv_bfloat16* __restrict__ kl,
    const __nv_bfloat16* __restrict__ vh, const __nv_bfloat16* __restrict__ vl,
    const float* __restrict__ bias, const float* __restrict__ mask,
    const float* __restrict__ c_attn,
    __nv_bfloat16* __restrict__ oh, __nv_bfloat16* __restrict__ ol)
{
    extern __shared__ __align__(128) char smem[];
    const uint32_t sb = smem_u32(smem);
    const int tid  = threadIdx.x;
    const int lane = tid & 31;
    const int wid  = tid >> 5;
    const int wm   = wid * 16;           // warp covers 16 q rows
    const int b    = blockIdx.y >> 4;
    const int h    = blockIdx.y & 15;
    const int q0   = blockIdx.x * 128;

    // loader mapping: row = tid>>1, segs (tid&1)*4 .. +3
    const int lr = tid >> 1;
    const int ls = (tid & 1) * 4;
    const size_t qg  = ((size_t)(b * Lt + q0 + lr)) * Ct + h * Dt + ls * 8;
    const size_t kg0 = ((size_t)(b * Lt + lr)) * Ct + h * Dt + ls * 8;
    uint32_t ldst[4];
#pragma unroll
    for (int i = 0; i < 4; i++) ldst[i] = off8(lr, ls + i);

    // load Q (group with tile 0)
#pragma unroll
    for (int i = 0; i < 4; i++) {
        CPASYNC16(sb + ldst[i],         qh + qg + i * 8);
        CPASYNC16(sb + 16384 + ldst[i], ql + qg + i * 8);
    }
#define FA_ISSUE(t)                                                            \
    do {                                                                       \
        const uint32_t bs_ = sb + 32768 + ((t) & 1) * 65536;                   \
        const size_t kof_ = kg0 + (size_t)(t) * 128 * Ct;                      \
        _Pragma("unroll")                                                      \
        for (int i = 0; i < 4; i++) {                                          \
            CPASYNC16(bs_ + 0     + ldst[i], kh + kof_ + i * 8);               \
            CPASYNC16(bs_ + 16384 + ldst[i], kl + kof_ + i * 8);               \
            CPASYNC16(bs_ + 32768 + ldst[i], vh + kof_ + i * 8);               \
            CPASYNC16(bs_ + 49152 + ldst[i], vl + kof_ + i * 8);               \
        }                                                                      \
        CPCOMMIT();                                                            \
    } while (0)

    FA_ISSUE(0);   // commits Q + tile0 as one group
    FA_ISSUE(1);

    const float* bias_b = bias + (size_t)blockIdx.y * Lt * Lt;
    const float* mask_b = mask + (size_t)b * Lt * Lt;
    const int row0 = q0 + wm + (lane >> 2);
    const int row1 = row0 + 8;

    float m0 = -1e30f, m1 = -1e30f, l0 = 0.0f, l1 = 0.0f;
    float o[8][4];
#pragma unroll
    for (int g = 0; g < 8; g++)
#pragma unroll
        for (int t = 0; t < 4; t++) o[g][t] = 0.0f;

    for (int t = 0; t < 8; t++) {
        if (t < 7) CPWAIT1(); else CPWAIT0();
        __syncthreads();
        const uint32_t kb = sb + 32768 + (t & 1) * 65536;

        // ---- S = Q K^T (3-term split) ----
        float sc[16][4];
#pragma unroll
        for (int j = 0; j < 16; j++)
#pragma unroll
            for (int e = 0; e < 4; e++) sc[j][e] = 0.0f;

#pragma unroll
        for (int ks = 0; ks < 4; ks++) {
            uint32_t aH[4], aL[4];
            const int ar = wm + (lane & 15);
            const int as_ = ks * 2 + (lane >> 4);
            LDMX4(aH[0], aH[1], aH[2], aH[3], sb + off8(ar, as_));
            LDMX4(aL[0], aL[1], aL[2], aL[3], sb + 16384 + off8(ar, as_));
            const int br = ((lane >> 4) & 1) * 8 + (lane & 7);
            const int bs2 = ks * 2 + ((lane >> 3) & 1);
#pragma unroll
            for (int j = 0; j < 8; j++) {
                uint32_t bh2[2][2], bl2[2][2];
                LDMX4(bh2[0][0], bh2[0][1], bh2[1][0], bh2[1][1],
                      kb + off8(j * 16 + br, bs2));
                LDMX4(bl2[0][0], bl2[0][1], bl2[1][0], bl2[1][1],
                      kb + 16384 + off8(j * 16 + br, bs2));
                MMA16816(sc[2 * j],     aH, bh2[0]);
                MMA16816(sc[2 * j + 1], aH, bh2[1]);
                MMA16816(sc[2 * j],     aH, bl2[0]);
                MMA16816(sc[2 * j + 1], aH, bl2[1]);
                MMA16816(sc[2 * j],     aL, bh2[0]);
                MMA16816(sc[2 * j + 1], aL, bh2[1]);
            }
        }

        // ---- scale + bias + mask, online softmax ----
        float tm0 = -1e30f, tm1 = -1e30f;
#pragma unroll
        for (int j = 0; j < 16; j++) {
            const int col = t * 128 + j * 8 + (lane & 3) * 2;
            const float2 b0 = *(const float2*)(bias_b + (size_t)row0 * Lt + col);
            const float2 b1 = *(const float2*)(bias_b + (size_t)row1 * Lt + col);
            const float2 mk0 = *(const float2*)(mask_b + (size_t)row0 * Lt + col);
            const float2 mk1 = *(const float2*)(mask_b + (size_t)row1 * Lt + col);
            sc[j][0] = sc[j][0] * SCALE + b0.x + mk0.x;
            sc[j][1] = sc[j][1] * SCALE + b0.y + mk0.y;
            sc[j][2] = sc[j][2] * SCALE + b1.x + mk1.x;
            sc[j][3] = sc[j][3] * SCALE + b1.y + mk1.y;
            tm0 = fmaxf(tm0, fmaxf(sc[j][0], sc[j][1]));
            tm1 = fmaxf(tm1, fmaxf(sc[j][2], sc[j][3]));
        }
        tm0 = fmaxf(tm0, __shfl_xor_sync(0xffffffffu, tm0, 1));
        tm0 = fmaxf(tm0, __shfl_xor_sync(0xffffffffu, tm0, 2));
        tm1 = fmaxf(tm1, __shfl_xor_sync(0xffffffffu, tm1, 1));
        tm1 = fmaxf(tm1, __shfl_xor_sync(0xffffffffu, tm1, 2));
        const float nm0 = fmaxf(m0, tm0), nm1 = fmaxf(m1, tm1);
        const float a0 = __expf(m0 - nm0), a1 = __expf(m1 - nm1);
        float ts0 = 0.0f, ts1 = 0.0f;
#pragma unroll
        for (int j = 0; j < 16; j++) {
            sc[j][0] = __expf(sc[j][0] - nm0);
            sc[j][1] = __expf(sc[j][1] - nm0);
            sc[j][2] = __expf(sc[j][2] - nm1);
            sc[j][3] = __expf(sc[j][3] - nm1);
            ts0 += sc[j][0] + sc[j][1];
            ts1 += sc[j][2] + sc[j][3];
        }
        ts0 += __shfl_xor_sync(0xffffffffu, ts0, 1);
        ts0 += __shfl_xor_sync(0xffffffffu, ts0, 2);
        ts1 += __shfl_xor_sync(0xffffffffu, ts1, 1);
        ts1 += __shfl_xor_sync(0xffffffffu, ts1, 2);
        l0 = l0 * a0 + ts0;
        l1 = l1 * a1 + ts1;
        m0 = nm0; m1 = nm1;
#pragma unroll
        for (int g = 0; g < 8; g++) {
            o[g][0] *= a0; o[g][1] *= a0; o[g][2] *= a1; o[g][3] *= a1;
        }

        // ---- O += P V (3-term split) ----
#pragma unroll
        for (int ks = 0; ks < 8; ks++) {
            uint32_t pH[4], pL[4];
            {
                const float e0 = sc[2 * ks][0],     e1 = sc[2 * ks][1];
                const float e2 = sc[2 * ks][2],     e3 = sc[2 * ks][3];
                const float f0 = sc[2 * ks + 1][0], f1 = sc[2 * ks + 1][1];
                const float f2 = sc[2 * ks + 1][2], f3 = sc[2 * ks + 1][3];
                __nv_bfloat162 h0 = __floats2bfloat162_rn(e0, e1);
                __nv_bfloat162 h1 = __floats2bfloat162_rn(e2, e3);
                __nv_bfloat162 h2 = __floats2bfloat162_rn(f0, f1);
                __nv_bfloat162 h3 = __floats2bfloat162_rn(f2, f3);
                pH[0] = *(uint32_t*)&h0; pH[1] = *(uint32_t*)&h1;
                pH[2] = *(uint32_t*)&h2; pH[3] = *(uint32_t*)&h3;
                pL[0] = packbf2(e0 - __low2float(h0), e1 - __high2float(h0));
                pL[1] = packbf2(e2 - __low2float(h1), e3 - __high2float(h1));
                pL[2] = packbf2(f0 - __low2float(h2), f1 - __high2float(h2));
                pL[3] = packbf2(f2 - __low2float(h3), f3 - __high2float(h3));
            }
            const int vr = ks * 16 + (lane & 15);
#pragma unroll
            for (int g = 0; g < 4; g++) {
                const int vs = g * 2 + (lane >> 4);
                uint32_t bvh[2][2], bvl[2][2];
                LDMX4T(bvh[0][0], bvh[0][1], bvh[1][0], bvh[1][1],
                       kb + 32768 + off8(vr, vs));
                LDMX4T(bvl[0][0], bvl[0][1], bvl[1][0], bvl[1][1],
                       kb + 49152 + off8(vr, vs));
                MMA16816(o[2 * g],     pH, bvh[0]);
                MMA16816(o[2 * g + 1], pH, bvh[1]);
                MMA16816(o[2 * g],     pH, bvl[0]);
                MMA16816(o[2 * g + 1], pH, bvl[1]);
                MMA16816(o[2 * g],     pL, bvh[0]);
                MMA16816(o[2 * g + 1], pL, bvh[1]);
            }
        }

        __syncthreads();
        if (t + 2 < 8) FA_ISSUE(t + 2);
    }
#undef FA_ISSUE

    // ---- epilogue: O/l * c_attn, split bf16, store at [b,l, h*64+d] ----
    const float cs = c_attn[h];
    const float i0 = cs / l0, i1 = cs / l1;
    const size_t gr0 = ((size_t)(b * Lt + row0)) * Ct + h * Dt + (lane & 3) * 2;
    const size_t gr1 = ((size_t)(b * Lt + row1)) * Ct + h * Dt + (lane & 3) * 2;
#pragma unroll
    for (int g = 0; g < 8; g++) {
        const float v0 = o[g][0] * i0, v1 = o[g][1] * i0;
        const float v2 = o[g][2] * i1, v3 = o[g][3] * i1;
        __nv_bfloat162 h0 = __floats2bfloat162_rn(v0, v1);
        __nv_bfloat162 h1 = __floats2bfloat162_rn(v2, v3);
        *(__nv_bfloat162*)(oh + gr0 + g * 8) = h0;
        *(__nv_bfloat162*)(oh + gr1 + g * 8) = h1;
        *(__nv_bfloat162*)(ol + gr0 + g * 8) =
            __floats2bfloat162_rn(v0 - __low2float(h0), v1 - __high2float(h0));
        *(__nv_bfloat162*)(ol + gr1 + g * 8) =
            __floats2bfloat162_rn(v2 - __low2float(h1), v3 - __high2float(h1));
    }
}

// ---------------- fp32 -> split bf16 (hi/lo) ----------------
__global__ __launch_bounds__(256) void split_bf16_kernel(
    const float* __restrict__ s, __nv_bfloat16* __restrict__ hi,
    __nv_bfloat16* __restrict__ lo, int n4)
{
    int i = blockIdx.x * 256 + threadIdx.x;
    if (i >= n4) return;
    float4 v = ((const float4*)s)[i];
    float vv[4] = {v.x, v.y, v.z, v.w};
#pragma unroll
    for (int k = 0; k < 4; k++) {
        __nv_bfloat16 h = __float2bfloat16(vv[k]);
        __nv_bfloat16 l = __float2bfloat16(vv[k] - __bfloat162float(h));
        hi[(size_t)i * 4 + k] = h;
        lo[(size_t)i * 4 + k] = l;
    }
}

// ---------------- layernorm -> split bf16 ----------------
__global__ __launch_bounds__(256) void ln_bf16_kernel(
    const float* __restrict__ in, const float* __restrict__ g, const float* __restrict__ be,
    __nv_bfloat16* __restrict__ hi, __nv_bfloat16* __restrict__ lo, int cols)
{
    const size_t base = (size_t)blockIdx.x * cols;
    const int tid = threadIdx.x;
    __shared__ float rs[32], rs2[32];

    float s = 0.0f, s2 = 0.0f;
    for (int c = tid; c < cols; c += 256) {
        float x = in[base + c];
        s += x; s2 += x * x;
    }
#pragma unroll
    for (int o = 16; o; o >>= 1) {
        s  += __shfl_xor_sync(0xffffffffu, s,  o);
        s2 += __shfl_xor_sync(0xffffffffu, s2, o);
    }
    if ((tid & 31) == 0) { rs[tid >> 5] = s; rs2[tid >> 5] = s2; }
    __syncthreads();
    if (tid == 0) {
        float a = 0.0f, a2 = 0.0f;
        for (int i = 0; i < 8; i++) { a += rs[i]; a2 += rs2[i]; }
        rs[0] = a; rs2[0] = a2;
    }
    __syncthreads();
    const float icols = 1.0f / (float)cols;
    const float mean = rs[0] * icols;
    const float var  = rs2[0] * icols - mean * mean;
    const float rstd = rsqrtf(var + 1e-5f);

    for (int c = tid; c < cols; c += 256) {
        float x = in[base + c];
        float val = (x - mean) * rstd * g[c] + be[c];
        __nv_bfloat16 h = __float2bfloat16(val);
        hi[base + c] = h;
        lo[base + c] = __float2bfloat16(val - __bfloat162float(h));
    }
}

// ---------------- layernorm fp32 (+residual) ----------------
template <bool RES>
__global__ __launch_bounds__(256) void ln_kernel(
    const float* __restrict__ in, const float* __restrict__ g, const float* __restrict__ be,
    const float* __restrict__ res, float* __restrict__ out, int cols)
{
    const size_t base = (size_t)blockIdx.x * cols;
    const int tid = threadIdx.x;
    __shared__ float rs[32], rs2[32];

    float s = 0.0f, s2 = 0.0f;
    for (int c = tid; c < cols; c += 256) {
        float x = in[base + c];
        s += x; s2 += x * x;
    }
#pragma unroll
    for (int o = 16; o; o >>= 1) {
        s  += __shfl_xor_sync(0xffffffffu, s,  o);
        s2 += __shfl_xor_sync(0xffffffffu, s2, o);
    }
    if ((tid & 31) == 0) { rs[tid >> 5] = s; rs2[tid >> 5] = s2; }
    __syncthreads();
    if (tid == 0) {
        float a = 0.0f, a2 = 0.0f;
        for (int i = 0; i < 8; i++) { a += rs[i]; a2 += rs2[i]; }
        rs[0] = a; rs2[0] = a2;
    }
    __syncthreads();
    const float icols = 1.0f / (float)cols;
    const float mean = rs[0] * icols;
    const float var  = rs2[0] * icols - mean * mean;
    const float rstd = rsqrtf(var + 1e-5f);

    for (int c = tid; c < cols; c += 256) {
        float x = in[base + c];
        float val = (x - mean) * rstd * g[c] + be[c];
        if (RES) val += res[base + c];
        out[base + c] = val;
    }
}

// ---------------- launch ----------------
extern "C" void kernel_launch(void* const* d_in, const int* in_sizes, int n_in,
                              void* d_out, int out_size)
{
    const float* x       = (const float*)d_in[0];
    const float* ab      = (const float*)d_in[1];
    const float* amask   = (const float*)d_in[2];
    const float* Wq      = (const float*)d_in[3];
    const float* bq      = (const float*)d_in[4];
    const float* Wk      = (const float*)d_in[5];
    const float* bk      = (const float*)d_in[6];
    const float* Wv      = (const float*)d_in[7];
    const float* bv      = (const float*)d_in[8];
    const float* Wo      = (const float*)d_in[9];
    const float* bo      = (const float*)d_in[10];
    const float* c_attn  = (const float*)d_in[11];
    const float* W1      = (const float*)d_in[12];
    const float* b1      = (const float*)d_in[13];
    const float* W2      = (const float*)d_in[14];
    const float* b2      = (const float*)d_in[15];
    const float* ln_g    = (const float*)d_in[16];
    const float* ln_b    = (const float*)d_in[17];
    const float* mln_g   = (const float*)d_in[18];
    const float* mln_b   = (const float*)d_in[19];
    const float* fln_g   = (const float*)d_in[20];
    const float* fln_b   = (const float*)d_in[21];
    const float* fmln_g  = (const float*)d_in[22];
    const float* fmln_b  = (const float*)d_in[23];
    float* out = (float*)d_out;

    float *proj_, *x1_, *ff_;
    __nv_bfloat16 *hh, *hl, *qh, *ql, *kh, *kl, *vh, *vl, *oh, *ol, *fh, *fl;
    __nv_bfloat16 *wqh, *wql, *wkh, *wkl, *wvh, *wvl, *woh, *wol, *w1h, *w1l, *w2h, *w2l;
    cudaGetSymbolAddress((void**)&proj_, g_proj);
    cudaGetSymbolAddress((void**)&x1_,   g_x1);
    cudaGetSymbolAddress((void**)&ff_,   g_ff);
    cudaGetSymbolAddress((void**)&hh, g_hh);   cudaGetSymbolAddress((void**)&hl, g_hl);
    cudaGetSymbolAddress((void**)&qh, g_qh);   cudaGetSymbolAddress((void**)&ql, g_ql);
    cudaGetSymbolAddress((void**)&kh, g_kh);   cudaGetSymbolAddress((void**)&kl, g_kl);
    cudaGetSymbolAddress((void**)&vh, g_vh);   cudaGetSymbolAddress((void**)&vl, g_vl);
    cudaGetSymbolAddress((void**)&oh, g_oh);   cudaGetSymbolAddress((void**)&ol, g_ol);
    cudaGetSymbolAddress((void**)&fh, g_fh);   cudaGetSymbolAddress((void**)&fl, g_fl);
    cudaGetSymbolAddress((void**)&wqh, g_wqh); cudaGetSymbolAddress((void**)&wql, g_wql);
    cudaGetSymbolAddress((void**)&wkh, g_wkh); cudaGetSymbolAddress((void**)&wkl, g_wkl);
    cudaGetSymbolAddress((void**)&wvh, g_wvh); cudaGetSymbolAddress((void**)&wvl, g_wvl);
    cudaGetSymbolAddress((void**)&woh, g_woh); cudaGetSymbolAddress((void**)&wol, g_wol);
    cudaGetSymbolAddress((void**)&w1h, g_w1h); cudaGetSymbolAddress((void**)&w1l, g_w1l);
    cudaGetSymbolAddress((void**)&w2h, g_w2h); cudaGetSymbolAddress((void**)&w2l, g_w2l);

    cudaFuncSetAttribute(hmma_gemm<EPI_BIAS>,  cudaFuncAttributeMaxDynamicSharedMemorySize, GEMM_SMEM);
    cudaFuncSetAttribute(hmma_gemm<EPI_GELU>,  cudaFuncAttributeMaxDynamicSharedMemorySize, GEMM_SMEM);
    cudaFuncSetAttribute(hmma_gemm<EPI_RES>,   cudaFuncAttributeMaxDynamicSharedMemorySize, GEMM_SMEM);
    cudaFuncSetAttribute(hmma_gemm<EPI_SPLIT>, cudaFuncAttributeMaxDynamicSharedMemorySize, GEMM_SMEM);
    cudaFuncSetAttribute(flash_attn, cudaFuncAttributeMaxDynamicSharedMemorySize, FA_SMEM);

    // weight splits
    const int nCC = Ct * Ct / 4, nFC = FFt * Ct / 4;
    split_bf16_kernel<<<nCC / 256, 256>>>(Wq, wqh, wql, nCC);
    split_bf16_kernel<<<nCC / 256, 256>>>(Wk, wkh, wkl, nCC);
    split_bf16_kernel<<<nCC / 256, 256>>>(Wv, wvh, wvl, nCC);
    split_bf16_kernel<<<nCC / 256, 256>>>(Wo, woh, wol, nCC);
    split_bf16_kernel<<<nFC / 256, 256>>>(W1, w1h, w1l, nFC);
    split_bf16_kernel<<<nFC / 256, 256>>>(W2, w2h, w2l, nFC);

    // ---- attention block ----
    ln_bf16_kernel<<<NTOK, 256>>>(x, ln_g, ln_b, hh, hl, Ct);

    dim3 gq(Ct / 128, NTOK / 128);
    hmma_gemm<EPI_SPLIT><<<gq, 256, GEMM_SMEM>>>(hh, hl, wqh, wql, bq, nullptr, nullptr, qh, ql, Ct, Ct);
    hmma_gemm<EPI_SPLIT><<<gq, 256, GEMM_SMEM>>>(hh, hl, wkh, wkl, bk, nullptr, nullptr, kh, kl, Ct, Ct);
    hmma_gemm<EPI_SPLIT><<<gq, 256, GEMM_SMEM>>>(hh, hl, wvh, wvl, bv, nullptr, nullptr, vh, vl, Ct, Ct);

    dim3 gfa(Lt / 128, Bb * Ht);   // (8, 64)
    flash_attn<<<gfa, 256, FA_SMEM>>>(qh, ql, kh, kl, vh, vl, ab, amask, c_attn, oh, ol);

    hmma_gemm<EPI_BIAS><<<gq, 256, GEMM_SMEM>>>(oh, ol, woh, wol, bo, nullptr, proj_, nullptr, nullptr, Ct, Ct);
    ln_kernel<true><<<NTOK, 256>>>(proj_, mln_g, mln_b, x, x1_, Ct);

    // ---- FFN block ----
    ln_bf16_kernel<<<NTOK, 256>>>(x1_, fln_g, fln_b, hh, hl, Ct);

    dim3 g1(FFt / 128, NTOK / 128);
    hmma_gemm<EPI_GELU><<<g1, 256, GEMM_SMEM>>>(hh, hl, w1h, w1l, b1, nullptr, ff_, nullptr, nullptr, FFt, Ct);

    ln_bf16_kernel<<<NTOK, 256>>>(ff_, fmln_g, fmln_b, fh, fl, FFt);

    hmma_gemm<EPI_RES><<<gq, 256, GEMM_SMEM>>>(fh, fl, w2h, w2l, b2, x1_, out, nullptr, nullptr, Ct, FFt);
}

// round 7
// speedup vs baseline: 1.5902x; 1.0682x over previous
#include <cuda_runtime.h>
#include <cuda_bf16.h>
#include <math.h>
#include <stdint.h>

// Problem constants
#define Bb   4
#define Lt   1024
#define Ct   1024
#define Ht   16
#define Dt   64
#define FFt  4096
#define NTOK (Bb * Lt)
#define SCALE 0.08838834764831843f

// ---------------- scratch (static device allocations; allowed) ----------------
static __device__ float g_proj[(size_t)NTOK * Ct];
static __device__ float g_x1  [(size_t)NTOK * Ct];
static __device__ float g_ff  [(size_t)NTOK * FFt];

// split-bf16 activations
static __device__ __align__(256) __nv_bfloat16 g_hh[(size_t)NTOK * Ct],  g_hl[(size_t)NTOK * Ct];
static __device__ __align__(256) __nv_bfloat16 g_qh[(size_t)NTOK * Ct],  g_ql[(size_t)NTOK * Ct];
static __device__ __align__(256) __nv_bfloat16 g_kh[(size_t)NTOK * Ct],  g_kl[(size_t)NTOK * Ct];
static __device__ __align__(256) __nv_bfloat16 g_vh[(size_t)NTOK * Ct],  g_vl[(size_t)NTOK * Ct];
static __device__ __align__(256) __nv_bfloat16 g_oh[(size_t)NTOK * Ct],  g_ol[(size_t)NTOK * Ct];
static __device__ __align__(256) __nv_bfloat16 g_fh[(size_t)NTOK * FFt], g_fl[(size_t)NTOK * FFt];
// split-bf16 weights
static __device__ __align__(256) __nv_bfloat16 g_wqh[(size_t)Ct * Ct],  g_wql[(size_t)Ct * Ct];
static __device__ __align__(256) __nv_bfloat16 g_wkh[(size_t)Ct * Ct],  g_wkl[(size_t)Ct * Ct];
static __device__ __align__(256) __nv_bfloat16 g_wvh[(size_t)Ct * Ct],  g_wvl[(size_t)Ct * Ct];
static __device__ __align__(256) __nv_bfloat16 g_woh[(size_t)Ct * Ct],  g_wol[(size_t)Ct * Ct];
static __device__ __align__(256) __nv_bfloat16 g_w1h[(size_t)FFt * Ct], g_w1l[(size_t)FFt * Ct];
static __device__ __align__(256) __nv_bfloat16 g_w2h[(size_t)Ct * FFt], g_w2l[(size_t)Ct * FFt];

__device__ __forceinline__ float gelu_exact(float x) {
    return 0.5f * x * (1.0f + erff(x * 0.70710678118654752f));
}

__device__ __forceinline__ uint32_t smem_u32(const void* p) {
    uint32_t a;
    asm("{ .reg .u64 t; cvta.to.shared.u64 t, %1; cvt.u32.u64 %0, t; }" : "=r"(a) : "l"(p));
    return a;
}

// ---------------- HMMA building blocks (base sm_103 features) -------
#define LDMX4(d0, d1, d2, d3, addr) \
    asm volatile("ldmatrix.sync.aligned.m8n8.x4.shared.b16 {%0,%1,%2,%3}, [%4];" \
                 : "=r"(d0), "=r"(d1), "=r"(d2), "=r"(d3) : "r"(addr))

#define LDMX4T(d0, d1, d2, d3, addr) \
    asm volatile("ldmatrix.sync.aligned.m8n8.x4.trans.shared.b16 {%0,%1,%2,%3}, [%4];" \
                 : "=r"(d0), "=r"(d1), "=r"(d2), "=r"(d3) : "r"(addr))

#define MMA16816(d, a, b) \
    asm volatile("mma.sync.aligned.m16n8k16.row.col.f32.bf16.bf16.f32 " \
                 "{%0,%1,%2,%3}, {%4,%5,%6,%7}, {%8,%9}, {%0,%1,%2,%3};" \
                 : "+f"((d)[0]), "+f"((d)[1]), "+f"((d)[2]), "+f"((d)[3]) \
                 : "r"((a)[0]), "r"((a)[1]), "r"((a)[2]), "r"((a)[3]), \
                   "r"((b)[0]), "r"((b)[1]))

#define CPASYNC16(saddr, gptr) \
    asm volatile("cp.async.cg.shared.global [%0], [%1], 16;" :: "r"(saddr), "l"(gptr))
#define CPCOMMIT() asm volatile("cp.async.commit_group;")
#define CPWAIT2()  asm volatile("cp.async.wait_group 2;")
#define CPWAIT1()  asm volatile("cp.async.wait_group 1;")
#define CPWAIT0()  asm volatile("cp.async.wait_group 0;")

// GEMM smem: 128 rows x 32 cols bf16 (64B rows, 4x16B segs), seg' = s ^ ((r>>1)&3)
__device__ __forceinline__ uint32_t swz(int r, int s) {
    return (uint32_t)(r * 64 + ((s ^ ((r >> 1) & 3)) << 4));
}
// Flash smem: 128 rows x 64 cols bf16 (128B rows, 8x16B segs), seg' = s ^ (r&7)
__device__ __forceinline__ uint32_t off8(int r, int s) {
    return (uint32_t)(r * 128 + ((s ^ (r & 7)) << 4));
}

__device__ __forceinline__ uint32_t packbf2(float x, float y) {
    __nv_bfloat162 t = __floats2bfloat162_rn(x, y);
    return *(uint32_t*)&t;
}

// ============================ dense GEMM =====================================
// CTA 128x128, 4 warps (64x64 warp tiles), BK=32, 3-stage cp.async pipeline.
#define STAGE 32768
#define NSTAGE 3
#define GEMM_SMEM (NSTAGE * STAGE)

enum { EPI_BIAS = 0, EPI_GELU = 1, EPI_RES = 2, EPI_SPLIT = 3 };

template <int EPI>
__global__ __launch_bounds__(128, 2) void hmma_gemm(
    const __nv_bfloat16* __restrict__ Ah, const __nv_bfloat16* __restrict__ Al,
    const __nv_bfloat16* __restrict__ Bh, const __nv_bfloat16* __restrict__ Bl,
    const float* __restrict__ bias, const float* __restrict__ res,
    float* __restrict__ C, __nv_bfloat16* __restrict__ Chi,
    __nv_bfloat16* __restrict__ Clo, int N, int K)
{
    extern __shared__ __align__(128) char smem[];
    const uint32_t sb = smem_u32(smem);
    const int tid  = threadIdx.x;
    const int lane = tid & 31;
    const int wid  = tid >> 5;           // 0..3
    const int wm   = (wid & 1) * 64;
    const int wn   = (wid >> 1) * 64;

    const __nv_bfloat16* gAh = Ah + (size_t)blockIdx.y * 128 * K;
    const __nv_bfloat16* gAl = Al + (size_t)blockIdx.y * 128 * K;
    const __nv_bfloat16* gBh = Bh + (size_t)blockIdx.x * 128 * K;
    const __nv_bfloat16* gBl = Bl + (size_t)blockIdx.x * 128 * K;

    const int nch = K >> 5;
    // loader: 128 threads, each thread: rows r0+32j (j=0..3), seg s0
    const int r0 = tid >> 2, s0 = tid & 3;
    uint32_t sw[4];
    size_t   go[4];
#pragma unroll
    for (int j = 0; j < 4; j++) {
        sw[j] = swz(r0 + 32 * j, s0);
        go[j] = (size_t)(r0 + 32 * j) * K + s0 * 8;
    }

#define ISSUE(c)                                                              \
    do {                                                                      \
        const uint32_t bs_ = sb + ((c) % NSTAGE) * STAGE;                     \
        const size_t kof_ = (size_t)(c) * 32;                                 \
        _Pragma("unroll")                                                     \
        for (int j = 0; j < 4; j++) {                                         \
            CPASYNC16(bs_ + 0     + sw[j], gAh + go[j] + kof_);               \
            CPASYNC16(bs_ + 8192  + sw[j], gAl + go[j] + kof_);               \
            CPASYNC16(bs_ + 16384 + sw[j], gBh + go[j] + kof_);               \
            CPASYNC16(bs_ + 24576 + sw[j], gBl + go[j] + kof_);               \
        }                                                                     \
        CPCOMMIT();                                                           \
    } while (0)

    ISSUE(0);
    ISSUE(1);
    ISSUE(2);

    float acc[4][8][4];
#pragma unroll
    for (int i = 0; i < 4; i++)
#pragma unroll
        for (int j = 0; j < 8; j++)
#pragma unroll
            for (int t = 0; t < 4; t++) acc[i][j][t] = 0.0f;

    for (int c = 0; c < nch; c++) {
        const int rem = nch - 1 - c;
        if (rem >= 2) CPWAIT2(); else if (rem == 1) CPWAIT1(); else CPWAIT0();
        __syncthreads();
        const uint32_t base = sb + (c % NSTAGE) * STAGE;

#pragma unroll
        for (int ks = 0; ks < 2; ks++) {
            uint32_t ah[4][4], al_[4][4], bh[8][2], bl_[8][2];
            const int ar  = wm + (lane & 15);
            const int as_ = ks * 2 + (lane >> 4);
#pragma unroll
            for (int mi = 0; mi < 4; mi++) {
                LDMX4(ah[mi][0], ah[mi][1], ah[mi][2], ah[mi][3],
                      base + swz(ar + mi * 16, as_));
                LDMX4(al_[mi][0], al_[mi][1], al_[mi][2], al_[mi][3],
                      base + 8192 + swz(ar + mi * 16, as_));
            }
            const int br  = ((lane >> 4) & 1) * 8 + (lane & 7);
            const int bs2 = ks * 2 + ((lane >> 3) & 1);
#pragma unroll
            for (int np = 0; np < 4; np++) {
                LDMX4(bh[np * 2][0], bh[np * 2][1], bh[np * 2 + 1][0], bh[np * 2 + 1][1],
                      base + 16384 + swz(wn + np * 16 + br, bs2));
                LDMX4(bl_[np * 2][0], bl_[np * 2][1], bl_[np * 2 + 1][0], bl_[np * 2 + 1][1],
                      base + 24576 + swz(wn + np * 16 + br, bs2));
            }
#pragma unroll
            for (int mi = 0; mi < 4; mi++)
#pragma unroll
                for (int nt = 0; nt < 8; nt++) MMA16816(acc[mi][nt], ah[mi], bh[nt]);
#pragma unroll
            for (int mi = 0; mi < 4; mi++)
#pragma unroll
                for (int nt = 0; nt < 8; nt++) MMA16816(acc[mi][nt], ah[mi], bl_[nt]);
#pragma unroll
            for (int mi = 0; mi < 4; mi++)
#pragma unroll
                for (int nt = 0; nt < 8; nt++) MMA16816(acc[mi][nt], al_[mi], bh[nt]);
        }

        __syncthreads();
        if (c + 3 < nch) ISSUE(c + 3);
    }
#undef ISSUE

    const int rbase = blockIdx.y * 128 + wm + (lane >> 2);
    const int cbase = blockIdx.x * 128 + wn + (lane & 3) * 2;
#pragma unroll
    for (int mi = 0; mi < 4; mi++) {
#pragma unroll
        for (int half = 0; half < 2; half++) {
            const int row = rbase + mi * 16 + half * 8;
            const size_t ro = (size_t)row * N;
#pragma unroll
            for (int nt = 0; nt < 8; nt++) {
                const int col = cbase + nt * 8;
                float v0 = acc[mi][nt][half * 2 + 0] + bias[col];
                float v1 = acc[mi][nt][half * 2 + 1] + bias[col + 1];
                if (EPI == EPI_GELU) { v0 = gelu_exact(v0); v1 = gelu_exact(v1); }
                if (EPI == EPI_RES)  { v0 += res[ro + col]; v1 += res[ro + col + 1]; }
                if (EPI == EPI_SPLIT) {
                    __nv_bfloat162 h2 = __floats2bfloat162_rn(v0, v1);
                    *(__nv_bfloat162*)(Chi + ro + col) = h2;
                    *(__nv_bfloat162*)(Clo + ro + col) =
                        __floats2bfloat162_rn(v0 - __low2float(h2), v1 - __high2float(h2));
                } else {
                    C[ro + col]     = v0;
                    C[ro + col + 1] = v1;
                }
            }
        }
    }
}

// ============================ flash attention ================================
// CTA: 128 q-rows of one (b,h). smem: Qh@0 Ql@16K, stage s@32K+s*64K: Kh,Kl,Vh,Vl.
#define FA_SMEM (32768 + 2 * 65536)

__global__ __launch_bounds__(256, 1) void flash_attn(
    const __nv_bfloat16* __restrict__ qh, const __nv_bfloat16* __restrict__ ql,
    const __nv_bfloat16* __restrict__ kh, const __nv_bfloat16* __restrict__ kl,
    const __nv_bfloat16* __restrict__ vh, const __nv_bfloat16* __restrict__ vl,
    const float* __restrict__ bias, const float* __restrict__ mask,
    const float* __restrict__ c_attn,
    __nv_bfloat16* __restrict__ oh, __nv_bfloat16* __restrict__ ol)
{
    extern __shared__ __align__(128) char smem[];
    const uint32_t sb = smem_u32(smem);
    const int tid  = threadIdx.x;
    const int lane = tid & 31;
    const int wid  = tid >> 5;
    const int wm   = wid * 16;
    const int b    = blockIdx.y >> 4;
    const int h    = blockIdx.y & 15;
    const int q0   = blockIdx.x * 128;

    const int lr = tid >> 1;
    const int ls = (tid & 1) * 4;
    const size_t qg  = ((size_t)(b * Lt + q0 + lr)) * Ct + h * Dt + ls * 8;
    const size_t kg0 = ((size_t)(b * Lt + lr)) * Ct + h * Dt + ls * 8;
    uint32_t ldst[4];
#pragma unroll
    for (int i = 0; i < 4; i++) ldst[i] = off8(lr, ls + i);

#pragma unroll
    for (int i = 0; i < 4; i++) {
        CPASYNC16(sb + ldst[i],         qh + qg + i * 8);
        CPASYNC16(sb + 16384 + ldst[i], ql + qg + i * 8);
    }
#define FA_ISSUE(t)                                                            \
    do {                                                                       \
        const uint32_t bs_ = sb + 32768 + ((t) & 1) * 65536;                   \
        const size_t kof_ = kg0 + (size_t)(t) * 128 * Ct;                      \
        _Pragma("unroll")                                                      \
        for (int i = 0; i < 4; i++) {                                          \
            CPASYNC16(bs_ + 0     + ldst[i], kh + kof_ + i * 8);               \
            CPASYNC16(bs_ + 16384 + ldst[i], kl + kof_ + i * 8);               \
            CPASYNC16(bs_ + 32768 + ldst[i], vh + kof_ + i * 8);               \
            CPASYNC16(bs_ + 49152 + ldst[i], vl + kof_ + i * 8);               \
        }                                                                      \
        CPCOMMIT();                                                            \
    } while (0)

    FA_ISSUE(0);
    FA_ISSUE(1);

    const float* bias_b = bias + (size_t)blockIdx.y * Lt * Lt;
    const float* mask_b = mask + (size_t)b * Lt * Lt;
    const int row0 = q0 + wm + (lane >> 2);
    const int row1 = row0 + 8;

    float m0 = -1e30f, m1 = -1e30f, l0 = 0.0f, l1 = 0.0f;
    float o[8][4];
#pragma unroll
    for (int g = 0; g < 8; g++)
#pragma unroll
        for (int t = 0; t < 4; t++) o[g][t] = 0.0f;

    for (int t = 0; t < 8; t++) {
        if (t < 7) CPWAIT1(); else CPWAIT0();
        __syncthreads();
        const uint32_t kb = sb + 32768 + (t & 1) * 65536;

        float sc[16][4];
#pragma unroll
        for (int j = 0; j < 16; j++)
#pragma unroll
            for (int e = 0; e < 4; e++) sc[j][e] = 0.0f;

#pragma unroll
        for (int ks = 0; ks < 4; ks++) {
            uint32_t aH[4], aL[4];
            const int ar = wm + (lane & 15);
            const int as_ = ks * 2 + (lane >> 4);
            LDMX4(aH[0], aH[1], aH[2], aH[3], sb + off8(ar, as_));
            LDMX4(aL[0], aL[1], aL[2], aL[3], sb + 16384 + off8(ar, as_));
            const int br = ((lane >> 4) & 1) * 8 + (lane & 7);
            const int bs2 = ks * 2 + ((lane >> 3) & 1);
#pragma unroll
            for (int j = 0; j < 8; j++) {
                uint32_t bh2[2][2], bl2[2][2];
                LDMX4(bh2[0][0], bh2[0][1], bh2[1][0], bh2[1][1],
                      kb + off8(j * 16 + br, bs2));
                LDMX4(bl2[0][0], bl2[0][1], bl2[1][0], bl2[1][1],
                      kb + 16384 + off8(j * 16 + br, bs2));
                MMA16816(sc[2 * j],     aH, bh2[0]);
                MMA16816(sc[2 * j + 1], aH, bh2[1]);
                MMA16816(sc[2 * j],     aH, bl2[0]);
                MMA16816(sc[2 * j + 1], aH, bl2[1]);
                MMA16816(sc[2 * j],     aL, bh2[0]);
                MMA16816(sc[2 * j + 1], aL, bh2[1]);
            }
        }

        float tm0 = -1e30f, tm1 = -1e30f;
#pragma unroll
        for (int j = 0; j < 16; j++) {
            const int col = t * 128 + j * 8 + (lane & 3) * 2;
            const float2 b0 = *(const float2*)(bias_b + (size_t)row0 * Lt + col);
            const float2 b1 = *(const float2*)(bias_b + (size_t)row1 * Lt + col);
            const float2 mk0 = *(const float2*)(mask_b + (size_t)row0 * Lt + col);
            const float2 mk1 = *(const float2*)(mask_b + (size_t)row1 * Lt + col);
            sc[j][0] = sc[j][0] * SCALE + b0.x + mk0.x;
            sc[j][1] = sc[j][1] * SCALE + b0.y + mk0.y;
            sc[j][2] = sc[j][2] * SCALE + b1.x + mk1.x;
            sc[j][3] = sc[j][3] * SCALE + b1.y + mk1.y;
            tm0 = fmaxf(tm0, fmaxf(sc[j][0], sc[j][1]));
            tm1 = fmaxf(tm1, fmaxf(sc[j][2], sc[j][3]));
        }
        tm0 = fmaxf(tm0, __shfl_xor_sync(0xffffffffu, tm0, 1));
        tm0 = fmaxf(tm0, __shfl_xor_sync(0xffffffffu, tm0, 2));
        tm1 = fmaxf(tm1, __shfl_xor_sync(0xffffffffu, tm1, 1));
        tm1 = fmaxf(tm1, __shfl_xor_sync(0xffffffffu, tm1, 2));
        const float nm0 = fmaxf(m0, tm0), nm1 = fmaxf(m1, tm1);
        const float a0 = __expf(m0 - nm0), a1 = __expf(m1 - nm1);
        float ts0 = 0.0f, ts1 = 0.0f;
#pragma unroll
        for (int j = 0; j < 16; j++) {
            sc[j][0] = __expf(sc[j][0] - nm0);
            sc[j][1] = __expf(sc[j][1] - nm0);
            sc[j][2] = __expf(sc[j][2] - nm1);
            sc[j][3] = __expf(sc[j][3] - nm1);
            ts0 += sc[j][0] + sc[j][1];
            ts1 += sc[j][2] + sc[j][3];
        }
        ts0 += __shfl_xor_sync(0xffffffffu, ts0, 1);
        ts0 += __shfl_xor_sync(0xffffffffu, ts0, 2);
        ts1 += __shfl_xor_sync(0xffffffffu, ts1, 1);
        ts1 += __shfl_xor_sync(0xffffffffu, ts1, 2);
        l0 = l0 * a0 + ts0;
        l1 = l1 * a1 + ts1;
        m0 = nm0; m1 = nm1;
#pragma unroll
        for (int g = 0; g < 8; g++) {
            o[g][0] *= a0; o[g][1] *= a0; o[g][2] *= a1; o[g][3] *= a1;
        }

#pragma unroll
        for (int ks = 0; ks < 8; ks++) {
            uint32_t pH[4], pL[4];
            {
                const float e0 = sc[2 * ks][0],     e1 = sc[2 * ks][1];
                const float e2 = sc[2 * ks][2],     e3 = sc[2 * ks][3];
                const float f0 = sc[2 * ks + 1][0], f1 = sc[2 * ks + 1][1];
                const float f2 = sc[2 * ks + 1][2], f3 = sc[2 * ks + 1][3];
                __nv_bfloat162 h0 = __floats2bfloat162_rn(e0, e1);
                __nv_bfloat162 h1 = __floats2bfloat162_rn(e2, e3);
                __nv_bfloat162 h2 = __floats2bfloat162_rn(f0, f1);
                __nv_bfloat162 h3 = __floats2bfloat162_rn(f2, f3);
                pH[0] = *(uint32_t*)&h0; pH[1] = *(uint32_t*)&h1;
                pH[2] = *(uint32_t*)&h2; pH[3] = *(uint32_t*)&h3;
                pL[0] = packbf2(e0 - __low2float(h0), e1 - __high2float(h0));
                pL[1] = packbf2(e2 - __low2float(h1), e3 - __high2float(h1));
                pL[2] = packbf2(f0 - __low2float(h2), f1 - __high2float(h2));
                pL[3] = packbf2(f2 - __low2float(h3), f3 - __high2float(h3));
            }
            const int vr = ks * 16 + (lane & 15);
#pragma unroll
            for (int g = 0; g < 4; g++) {
                const int vs = g * 2 + (lane >> 4);
                uint32_t bvh[2][2], bvl[2][2];
                LDMX4T(bvh[0][0], bvh[0][1], bvh[1][0], bvh[1][1],
                       kb + 32768 + off8(vr, vs));
                LDMX4T(bvl[0][0], bvl[0][1], bvl[1][0], bvl[1][1],
                       kb + 49152 + off8(vr, vs));
                MMA16816(o[2 * g],     pH, bvh[0]);
                MMA16816(o[2 * g + 1], pH, bvh[1]);
                MMA16816(o[2 * g],     pH, bvl[0]);
                MMA16816(o[2 * g + 1], pH, bvl[1]);
                MMA16816(o[2 * g],     pL, bvh[0]);
                MMA16816(o[2 * g + 1], pL, bvh[1]);
            }
        }

        __syncthreads();
        if (t + 2 < 8) FA_ISSUE(t + 2);
    }
#undef FA_ISSUE

    const float cs = c_attn[h];
    const float i0 = cs / l0, i1 = cs / l1;
    const size_t gr0 = ((size_t)(b * Lt + row0)) * Ct + h * Dt + (lane & 3) * 2;
    const size_t gr1 = ((size_t)(b * Lt + row1)) * Ct + h * Dt + (lane & 3) * 2;
#pragma unroll
    for (int g = 0; g < 8; g++) {
        const float v0 = o[g][0] * i0, v1 = o[g][1] * i0;
        const float v2 = o[g][2] * i1, v3 = o[g][3] * i1;
        __nv_bfloat162 h0 = __floats2bfloat162_rn(v0, v1);
        __nv_bfloat162 h1 = __floats2bfloat162_rn(v2, v3);
        *(__nv_bfloat162*)(oh + gr0 + g * 8) = h0;
        *(__nv_bfloat162*)(oh + gr1 + g * 8) = h1;
        *(__nv_bfloat162*)(ol + gr0 + g * 8) =
            __floats2bfloat162_rn(v0 - __low2float(h0), v1 - __high2float(h0));
        *(__nv_bfloat162*)(ol + gr1 + g * 8) =
            __floats2bfloat162_rn(v2 - __low2float(h1), v3 - __high2float(h1));
    }
}

// ---------------- fp32 -> split bf16 (hi/lo) ----------------
__global__ __launch_bounds__(256) void split_bf16_kernel(
    const float* __restrict__ s, __nv_bfloat16* __restrict__ hi,
    __nv_bfloat16* __restrict__ lo, int n4)
{
    int i = blockIdx.x * 256 + threadIdx.x;
    if (i >= n4) return;
    float4 v = ((const float4*)s)[i];
    float vv[4] = {v.x, v.y, v.z, v.w};
#pragma unroll
    for (int k = 0; k < 4; k++) {
        __nv_bfloat16 h = __float2bfloat16(vv[k]);
        __nv_bfloat16 l = __float2bfloat16(vv[k] - __bfloat162float(h));
        hi[(size_t)i * 4 + k] = h;
        lo[(size_t)i * 4 + k] = l;
    }
}

// ---------------- layernorm -> split bf16 ----------------
__global__ __launch_bounds__(256) void ln_bf16_kernel(
    const float* __restrict__ in, const float* __restrict__ g, const float* __restrict__ be,
    __nv_bfloat16* __restrict__ hi, __nv_bfloat16* __restrict__ lo, int cols)
{
    const size_t base = (size_t)blockIdx.x * cols;
    const int tid = threadIdx.x;
    __shared__ float rs[32], rs2[32];

    float s = 0.0f, s2 = 0.0f;
    for (int c = tid; c < cols; c += 256) {
        float x = in[base + c];
        s += x; s2 += x * x;
    }
#pragma unroll
    for (int o = 16; o; o >>= 1) {
        s  += __shfl_xor_sync(0xffffffffu, s,  o);
        s2 += __shfl_xor_sync(0xffffffffu, s2, o);
    }
    if ((tid & 31) == 0) { rs[tid >> 5] = s; rs2[tid >> 5] = s2; }
    __syncthreads();
    if (tid == 0) {
        float a = 0.0f, a2 = 0.0f;
        for (int i = 0; i < 8; i++) { a += rs[i]; a2 += rs2[i]; }
        rs[0] = a; rs2[0] = a2;
    }
    __syncthreads();
    const float icols = 1.0f / (float)cols;
    const float mean = rs[0] * icols;
    const float var  = rs2[0] * icols - mean * mean;
    const float rstd = rsqrtf(var + 1e-5f);

    for (int c = tid; c < cols; c += 256) {
        float x = in[base + c];
        float val = (x - mean) * rstd * g[c] + be[c];
        __nv_bfloat16 h = __float2bfloat16(val);
        hi[base + c] = h;
        lo[base + c] = __float2bfloat16(val - __bfloat162float(h));
    }
}

// ---------------- layernorm fp32 (+residual) ----------------
template <bool RES>
__global__ __launch_bounds__(256) void ln_kernel(
    const float* __restrict__ in, const float* __restrict__ g, const float* __restrict__ be,
    const float* __restrict__ res, float* __restrict__ out, int cols)
{
    const size_t base = (size_t)blockIdx.x * cols;
    const int tid = threadIdx.x;
    __shared__ float rs[32], rs2[32];

    float s = 0.0f, s2 = 0.0f;
    for (int c = tid; c < cols; c += 256) {
        float x = in[base + c];
        s += x; s2 += x * x;
    }
#pragma unroll
    for (int o = 16; o; o >>= 1) {
        s  += __shfl_xor_sync(0xffffffffu, s,  o);
        s2 += __shfl_xor_sync(0xffffffffu, s2, o);
    }
    if ((tid & 31) == 0) { rs[tid >> 5] = s; rs2[tid >> 5] = s2; }
    __syncthreads();
    if (tid == 0) {
        float a = 0.0f, a2 = 0.0f;
        for (int i = 0; i < 8; i++) { a += rs[i]; a2 += rs2[i]; }
        rs[0] = a; rs2[0] = a2;
    }
    __syncthreads();
    const float icols = 1.0f / (float)cols;
    const float mean = rs[0] * icols;
    const float var  = rs2[0] * icols - mean * mean;
    const float rstd = rsqrtf(var + 1e-5f);

    for (int c = tid; c < cols; c += 256) {
        float x = in[base + c];
        float val = (x - mean) * rstd * g[c] + be[c];
        if (RES) val += res[base + c];
        out[base + c] = val;
    }
}

// ---------------- launch ----------------
extern "C" void kernel_launch(void* const* d_in, const int* in_sizes, int n_in,
                              void* d_out, int out_size)
{
    const float* x       = (const float*)d_in[0];
    const float* ab      = (const float*)d_in[1];
    const float* amask   = (const float*)d_in[2];
    const float* Wq      = (const float*)d_in[3];
    const float* bq      = (const float*)d_in[4];
    const float* Wk      = (const float*)d_in[5];
    const float* bk      = (const float*)d_in[6];
    const float* Wv      = (const float*)d_in[7];
    const float* bv      = (const float*)d_in[8];
    const float* Wo      = (const float*)d_in[9];
    const float* bo      = (const float*)d_in[10];
    const float* c_attn  = (const float*)d_in[11];
    const float* W1      = (const float*)d_in[12];
    const float* b1      = (const float*)d_in[13];
    const float* W2      = (const float*)d_in[14];
    const float* b2      = (const float*)d_in[15];
    const float* ln_g    = (const float*)d_in[16];
    const float* ln_b    = (const float*)d_in[17];
    const float* mln_g   = (const float*)d_in[18];
    const float* mln_b   = (const float*)d_in[19];
    const float* fln_g   = (const float*)d_in[20];
    const float* fln_b   = (const float*)d_in[21];
    const float* fmln_g  = (const float*)d_in[22];
    const float* fmln_b  = (const float*)d_in[23];
    float* out = (float*)d_out;

    float *proj_, *x1_, *ff_;
    __nv_bfloat16 *hh, *hl, *qh, *ql, *kh, *kl, *vh, *vl, *oh, *ol, *fh, *fl;
    __nv_bfloat16 *wqh, *wql, *wkh, *wkl, *wvh, *wvl, *woh, *wol, *w1h, *w1l, *w2h, *w2l;
    cudaGetSymbolAddress((void**)&proj_, g_proj);
    cudaGetSymbolAddress((void**)&x1_,   g_x1);
    cudaGetSymbolAddress((void**)&ff_,   g_ff);
    cudaGetSymbolAddress((void**)&hh, g_hh);   cudaGetSymbolAddress((void**)&hl, g_hl);
    cudaGetSymbolAddress((void**)&qh, g_qh);   cudaGetSymbolAddress((void**)&ql, g_ql);
    cudaGetSymbolAddress((void**)&kh, g_kh);   cudaGetSymbolAddress((void**)&kl, g_kl);
    cudaGetSymbolAddress((void**)&vh, g_vh);   cudaGetSymbolAddress((void**)&vl, g_vl);
    cudaGetSymbolAddress((void**)&oh, g_oh);   cudaGetSymbolAddress((void**)&ol, g_ol);
    cudaGetSymbolAddress((void**)&fh, g_fh);   cudaGetSymbolAddress((void**)&fl, g_fl);
    cudaGetSymbolAddress((void**)&wqh, g_wqh); cudaGetSymbolAddress((void**)&wql, g_wql);
    cudaGetSymbolAddress((void**)&wkh, g_wkh); cudaGetSymbolAddress((void**)&wkl, g_wkl);
    cudaGetSymbolAddress((void**)&wvh, g_wvh); cudaGetSymbolAddress((void**)&wvl, g_wvl);
    cudaGetSymbolAddress((void**)&woh, g_woh); cudaGetSymbolAddress((void**)&wol, g_wol);
    cudaGetSymbolAddress((void**)&w1h, g_w1h); cudaGetSymbolAddress((void**)&w1l, g_w1l);
    cudaGetSymbolAddress((void**)&w2h, g_w2h); cudaGetSymbolAddress((void**)&w2l, g_w2l);

    cudaFuncSetAttribute(hmma_gemm<EPI_BIAS>,  cudaFuncAttributeMaxDynamicSharedMemorySize, GEMM_SMEM);
    cudaFuncSetAttribute(hmma_gemm<EPI_GELU>,  cudaFuncAttributeMaxDynamicSharedMemorySize, GEMM_SMEM);
    cudaFuncSetAttribute(hmma_gemm<EPI_RES>,   cudaFuncAttributeMaxDynamicSharedMemorySize, GEMM_SMEM);
    cudaFuncSetAttribute(hmma_gemm<EPI_SPLIT>, cudaFuncAttributeMaxDynamicSharedMemorySize, GEMM_SMEM);
    cudaFuncSetAttribute(flash_attn, cudaFuncAttributeMaxDynamicSharedMemorySize, FA_SMEM);

    // weight splits
    const int nCC = Ct * Ct / 4, nFC = FFt * Ct / 4;
    split_bf16_kernel<<<nCC / 256, 256>>>(Wq, wqh, wql, nCC);
    split_bf16_kernel<<<nCC / 256, 256>>>(Wk, wkh, wkl, nCC);
    split_bf16_kernel<<<nCC / 256, 256>>>(Wv, wvh, wvl, nCC);
    split_bf16_kernel<<<nCC / 256, 256>>>(Wo, woh, wol, nCC);
    split_bf16_kernel<<<nFC / 256, 256>>>(W1, w1h, w1l, nFC);
    split_bf16_kernel<<<nFC / 256, 256>>>(W2, w2h, w2l, nFC);

    // ---- attention block ----
    ln_bf16_kernel<<<NTOK, 256>>>(x, ln_g, ln_b, hh, hl, Ct);

    dim3 gq(Ct / 128, NTOK / 128);
    hmma_gemm<EPI_SPLIT><<<gq, 128, GEMM_SMEM>>>(hh, hl, wqh, wql, bq, nullptr, nullptr, qh, ql, Ct, Ct);
    hmma_gemm<EPI_SPLIT><<<gq, 128, GEMM_SMEM>>>(hh, hl, wkh, wkl, bk, nullptr, nullptr, kh, kl, Ct, Ct);
    hmma_gemm<EPI_SPLIT><<<gq, 128, GEMM_SMEM>>>(hh, hl, wvh, wvl, bv, nullptr, nullptr, vh, vl, Ct, Ct);

    dim3 gfa(Lt / 128, Bb * Ht);   // (8, 64)
    flash_attn<<<gfa, 256, FA_SMEM>>>(qh, ql, kh, kl, vh, vl, ab, amask, c_attn, oh, ol);

    hmma_gemm<EPI_BIAS><<<gq, 128, GEMM_SMEM>>>(oh, ol, woh, wol, bo, nullptr, proj_, nullptr, nullptr, Ct, Ct);
    ln_kernel<true><<<NTOK, 256>>>(proj_, mln_g, mln_b, x, x1_, Ct);

    // ---- FFN block ----
    ln_bf16_kernel<<<NTOK, 256>>>(x1_, fln_g, fln_b, hh, hl, Ct);

    dim3 g1(FFt / 128, NTOK / 128);
    hmma_gemm<EPI_GELU><<<g1, 128, GEMM_SMEM>>>(hh, hl, w1h, w1l, b1, nullptr, ff_, nullptr, nullptr, FFt, Ct);

    ln_bf16_kernel<<<NTOK, 256>>>(ff_, fmln_g, fmln_b, fh, fl, FFt);

    hmma_gemm<EPI_RES><<<gq, 128, GEMM_SMEM>>>(fh, fl, w2h, w2l, b2, x1_, out, nullptr, nullptr, Ct, FFt);
}

// round 8
// speedup vs baseline: 1.8789x; 1.1816x over previous
#include <cuda_runtime.h>
#include <cuda_bf16.h>
#include <math.h>
#include <stdint.h>

// Problem constants
#define Bb   4
#define Lt   1024
#define Ct   1024
#define Ht   16
#define Dt   64
#define FFt  4096
#define NTOK (Bb * Lt)
#define SCALE 0.08838834764831843f

// ---------------- scratch ----------------
static __device__ float g_h   [(size_t)NTOK * Ct];
static __device__ float g_attn[(size_t)NTOK * Ct];
static __device__ float g_proj[(size_t)NTOK * Ct];
static __device__ float g_x1  [(size_t)NTOK * Ct];
static __device__ float g_ff  [(size_t)NTOK * FFt];

// split-bf16 buffers for flash attention only
static __device__ __align__(256) __nv_bfloat16 g_qh[(size_t)NTOK * Ct], g_ql[(size_t)NTOK * Ct];
static __device__ __align__(256) __nv_bfloat16 g_kh[(size_t)NTOK * Ct], g_kl[(size_t)NTOK * Ct];
static __device__ __align__(256) __nv_bfloat16 g_vh[(size_t)NTOK * Ct], g_vl[(size_t)NTOK * Ct];

__device__ __forceinline__ float gelu_exact(float x) {
    return 0.5f * x * (1.0f + erff(x * 0.70710678118654752f));
}

__device__ __forceinline__ uint32_t smem_u32(const void* p) {
    uint32_t a;
    asm("{ .reg .u64 t; cvta.to.shared.u64 t, %1; cvt.u32.u64 %0, t; }" : "=r"(a) : "l"(p));
    return a;
}

// ---------------- MMA building blocks (base sm_103 features) -------
#define LDMX4(d0, d1, d2, d3, addr) \
    asm volatile("ldmatrix.sync.aligned.m8n8.x4.shared.b16 {%0,%1,%2,%3}, [%4];" \
                 : "=r"(d0), "=r"(d1), "=r"(d2), "=r"(d3) : "r"(addr))

#define LDMX4T(d0, d1, d2, d3, addr) \
    asm volatile("ldmatrix.sync.aligned.m8n8.x4.trans.shared.b16 {%0,%1,%2,%3}, [%4];" \
                 : "=r"(d0), "=r"(d1), "=r"(d2), "=r"(d3) : "r"(addr))

#define MMA16816(d, a, b) \
    asm volatile("mma.sync.aligned.m16n8k16.row.col.f32.bf16.bf16.f32 " \
                 "{%0,%1,%2,%3}, {%4,%5,%6,%7}, {%8,%9}, {%0,%1,%2,%3};" \
                 : "+f"((d)[0]), "+f"((d)[1]), "+f"((d)[2]), "+f"((d)[3]) \
                 : "r"((a)[0]), "r"((a)[1]), "r"((a)[2]), "r"((a)[3]), \
                   "r"((b)[0]), "r"((b)[1]))

#define MMATF32(d, a, b) \
    asm volatile("mma.sync.aligned.m16n8k8.row.col.f32.tf32.tf32.f32 " \
                 "{%0,%1,%2,%3}, {%4,%5,%6,%7}, {%8,%9}, {%0,%1,%2,%3};" \
                 : "+f"((d)[0]), "+f"((d)[1]), "+f"((d)[2]), "+f"((d)[3]) \
                 : "r"((a)[0]), "r"((a)[1]), "r"((a)[2]), "r"((a)[3]), \
                   "r"((b)[0]), "r"((b)[1]))

#define CPASYNC16(saddr, gptr) \
    asm volatile("cp.async.cg.shared.global [%0], [%1], 16;" :: "r"(saddr), "l"(gptr))
#define CPCOMMIT() asm volatile("cp.async.commit_group;")
#define CPWAIT2()  asm volatile("cp.async.wait_group 2;")
#define CPWAIT1()  asm volatile("cp.async.wait_group 1;")
#define CPWAIT0()  asm volatile("cp.async.wait_group 0;")

// round-to-nearest tf32 in register
__device__ __forceinline__ uint32_t rna(uint32_t x) {
    uint32_t r;
    asm("cvt.rna.tf32.f32 %0, %1;" : "=r"(r) : "f"(__uint_as_float(x)));
    return r;
}

// 128B rows, 8x16B segs, seg' = s ^ (r&7)  -> conflict-free ldmatrix & cp.async
__device__ __forceinline__ uint32_t off8(int r, int s) {
    return (uint32_t)(r * 128 + ((s ^ (r & 7)) << 4));
}

__device__ __forceinline__ uint32_t packbf2(float x, float y) {
    __nv_bfloat162 t = __floats2bfloat162_rn(x, y);
    return *(uint32_t*)&t;
}

// ============================ tf32 dense GEMM ================================
// C[M,N] = A[M,K]fp32 @ W[N,K]fp32^T + bias (+epi). CTA 128x128, 4 warps
// (64x64 tiles), BK=32 fp32, 3-stage cp.async, rna-rounded tf32 single term.
#define STAGE 32768
#define NSTAGE 3
#define GEMM_SMEM (NSTAGE * STAGE)

enum { EPI_BIAS = 0, EPI_GELU = 1, EPI_RES = 2, EPI_SPLIT = 3 };

template <int EPI>
__global__ __launch_bounds__(128, 2) void tf32_gemm(
    const float* __restrict__ A, const float* __restrict__ W,
    const float* __restrict__ bias, const float* __restrict__ res,
    float* __restrict__ C, __nv_bfloat16* __restrict__ Chi,
    __nv_bfloat16* __restrict__ Clo, int N, int K)
{
    extern __shared__ __align__(128) char smem[];
    const uint32_t sb = smem_u32(smem);
    const int tid  = threadIdx.x;
    const int lane = tid & 31;
    const int wid  = tid >> 5;
    const int wm   = (wid & 1) * 64;
    const int wn   = (wid >> 1) * 64;

    const float* gA = A + (size_t)blockIdx.y * 128 * K;
    const float* gW = W + (size_t)blockIdx.x * 128 * K;

    const int nch = K >> 5;                 // 32 fp32 per chunk (128B rows)
    const int s0 = tid & 7;                 // seg
    const int rb = tid >> 3;                // 0..15
    uint32_t sw[8];
    size_t   go[8];
#pragma unroll
    for (int j = 0; j < 8; j++) {
        const int row = rb + 16 * j;
        sw[j] = off8(row, s0);
        go[j] = (size_t)row * K + s0 * 4;
    }

#define ISSUE(c)                                                              \
    do {                                                                      \
        const uint32_t bs_ = sb + ((c) % NSTAGE) * STAGE;                     \
        const size_t kof_ = (size_t)(c) * 32;                                 \
        _Pragma("unroll")                                                     \
        for (int j = 0; j < 8; j++) {                                         \
            CPASYNC16(bs_ + sw[j],         gA + go[j] + kof_);                \
            CPASYNC16(bs_ + 16384 + sw[j], gW + go[j] + kof_);                \
        }                                                                     \
        CPCOMMIT();                                                           \
    } while (0)

    ISSUE(0);
    ISSUE(1);
    ISSUE(2);

    float acc[4][8][4];
#pragma unroll
    for (int i = 0; i < 4; i++)
#pragma unroll
        for (int j = 0; j < 8; j++)
#pragma unroll
            for (int t = 0; t < 4; t++) acc[i][j][t] = 0.0f;

    for (int c = 0; c < nch; c++) {
        const int rem = nch - 1 - c;
        if (rem >= 2) CPWAIT2(); else if (rem == 1) CPWAIT1(); else CPWAIT0();
        __syncthreads();
        const uint32_t base = sb + (c % NSTAGE) * STAGE;

#pragma unroll
        for (int ks = 0; ks < 4; ks++) {     // 4 x k8 per 32-float chunk
            uint32_t af[4][4], bf[8][2];
            // A fragments: 8x4-fp32 tiles via b16 ldmatrix reinterpretation
            const int ar  = wm + (lane & 15);
            const int as_ = ks * 2 + (lane >> 4);
#pragma unroll
            for (int mi = 0; mi < 4; mi++) {
                LDMX4(af[mi][0], af[mi][1], af[mi][2], af[mi][3],
                      base + off8(ar + mi * 16, as_));
#pragma unroll
                for (int e = 0; e < 4; e++) af[mi][e] = rna(af[mi][e]);
            }
            // B fragments
            const int br  = ((lane >> 4) & 1) * 8 + (lane & 7);
            const int bs2 = ks * 2 + ((lane >> 3) & 1);
#pragma unroll
            for (int np = 0; np < 4; np++) {
                uint32_t d0, d1, d2, d3;
                LDMX4(d0, d1, d2, d3, base + 16384 + off8(wn + np * 16 + br, bs2));
                bf[np * 2][0]     = rna(d0);
                bf[np * 2][1]     = rna(d1);
                bf[np * 2 + 1][0] = rna(d2);
                bf[np * 2 + 1][1] = rna(d3);
            }
#pragma unroll
            for (int mi = 0; mi < 4; mi++)
#pragma unroll
                for (int nt = 0; nt < 8; nt++) MMATF32(acc[mi][nt], af[mi], bf[nt]);
        }

        __syncthreads();
        if (c + 3 < nch) ISSUE(c + 3);
    }
#undef ISSUE

    const int rbase = blockIdx.y * 128 + wm + (lane >> 2);
    const int cbase = blockIdx.x * 128 + wn + (lane & 3) * 2;
#pragma unroll
    for (int mi = 0; mi < 4; mi++) {
#pragma unroll
        for (int half = 0; half < 2; half++) {
            const int row = rbase + mi * 16 + half * 8;
            const size_t ro = (size_t)row * N;
#pragma unroll
            for (int nt = 0; nt < 8; nt++) {
                const int col = cbase + nt * 8;
                float v0 = acc[mi][nt][half * 2 + 0] + bias[col];
                float v1 = acc[mi][nt][half * 2 + 1] + bias[col + 1];
                if (EPI == EPI_GELU) { v0 = gelu_exact(v0); v1 = gelu_exact(v1); }
                if (EPI == EPI_RES)  { v0 += res[ro + col]; v1 += res[ro + col + 1]; }
                if (EPI == EPI_SPLIT) {
                    __nv_bfloat162 h2 = __floats2bfloat162_rn(v0, v1);
                    *(__nv_bfloat162*)(Chi + ro + col) = h2;
                    *(__nv_bfloat162*)(Clo + ro + col) =
                        __floats2bfloat162_rn(v0 - __low2float(h2), v1 - __high2float(h2));
                } else {
                    C[ro + col]     = v0;
                    C[ro + col + 1] = v1;
                }
            }
        }
    }
}

// ============================ flash attention ================================
// CTA: 128 q-rows of one (b,h). smem: Qh@0 Ql@16K, stage s@32K+s*64K: Kh,Kl,Vh,Vl.
#define FA_SMEM (32768 + 2 * 65536)

__global__ __launch_bounds__(256, 1) void flash_attn(
    const __nv_bfloat16* __restrict__ qh, const __nv_bfloat16* __restrict__ ql,
    const __nv_bfloat16* __restrict__ kh, const __nv_bfloat16* __restrict__ kl,
    const __nv_bfloat16* __restrict__ vh, const __nv_bfloat16* __restrict__ vl,
    const float* __restrict__ bias, const float* __restrict__ mask,
    const float* __restrict__ c_attn, float* __restrict__ outp)
{
    extern __shared__ __align__(128) char smem[];
    const uint32_t sb = smem_u32(smem);
    const int tid  = threadIdx.x;
    const int lane = tid & 31;
    const int wid  = tid >> 5;
    const int wm   = wid * 16;
    const int b    = blockIdx.y >> 4;
    const int h    = blockIdx.y & 15;
    const int q0   = blockIdx.x * 128;

    const int lr = tid >> 1;
    const int ls = (tid & 1) * 4;
    const size_t qg  = ((size_t)(b * Lt + q0 + lr)) * Ct + h * Dt + ls * 8;
    const size_t kg0 = ((size_t)(b * Lt + lr)) * Ct + h * Dt + ls * 8;
    uint32_t ldst[4];
#pragma unroll
    for (int i = 0; i < 4; i++) ldst[i] = off8(lr, ls + i);

#pragma unroll
    for (int i = 0; i < 4; i++) {
        CPASYNC16(sb + ldst[i],         qh + qg + i * 8);
        CPASYNC16(sb + 16384 + ldst[i], ql + qg + i * 8);
    }
#define FA_ISSUE(t)                                                            \
    do {                                                                       \
        const uint32_t bs_ = sb + 32768 + ((t) & 1) * 65536;                   \
        const size_t kof_ = kg0 + (size_t)(t) * 128 * Ct;                      \
        _Pragma("unroll")                                                      \
        for (int i = 0; i < 4; i++) {                                          \
            CPASYNC16(bs_ + 0     + ldst[i], kh + kof_ + i * 8);               \
            CPASYNC16(bs_ + 16384 + ldst[i], kl + kof_ + i * 8);               \
            CPASYNC16(bs_ + 32768 + ldst[i], vh + kof_ + i * 8);               \
            CPASYNC16(bs_ + 49152 + ldst[i], vl + kof_ + i * 8);               \
        }                                                                      \
        CPCOMMIT();                                                            \
    } while (0)

    FA_ISSUE(0);
    FA_ISSUE(1);

    const float* bias_b = bias + (size_t)blockIdx.y * Lt * Lt;
    const float* mask_b = mask + (size_t)b * Lt * Lt;
    const int row0 = q0 + wm + (lane >> 2);
    const int row1 = row0 + 8;

    float m0 = -1e30f, m1 = -1e30f, l0 = 0.0f, l1 = 0.0f;
    float o[8][4];
#pragma unroll
    for (int g = 0; g < 8; g++)
#pragma unroll
        for (int t = 0; t < 4; t++) o[g][t] = 0.0f;

    for (int t = 0; t < 8; t++) {
        if (t < 7) CPWAIT1(); else CPWAIT0();
        __syncthreads();
        const uint32_t kb = sb + 32768 + (t & 1) * 65536;

        float sc[16][4];
#pragma unroll
        for (int j = 0; j < 16; j++)
#pragma unroll
            for (int e = 0; e < 4; e++) sc[j][e] = 0.0f;

#pragma unroll
        for (int ks = 0; ks < 4; ks++) {
            uint32_t aH[4], aL[4];
            const int ar = wm + (lane & 15);
            const int as_ = ks * 2 + (lane >> 4);
            LDMX4(aH[0], aH[1], aH[2], aH[3], sb + off8(ar, as_));
            LDMX4(aL[0], aL[1], aL[2], aL[3], sb + 16384 + off8(ar, as_));
            const int br = ((lane >> 4) & 1) * 8 + (lane & 7);
            const int bs2 = ks * 2 + ((lane >> 3) & 1);
#pragma unroll
            for (int j = 0; j < 8; j++) {
                uint32_t bh2[2][2], bl2[2][2];
                LDMX4(bh2[0][0], bh2[0][1], bh2[1][0], bh2[1][1],
                      kb + off8(j * 16 + br, bs2));
                LDMX4(bl2[0][0], bl2[0][1], bl2[1][0], bl2[1][1],
                      kb + 16384 + off8(j * 16 + br, bs2));
                MMA16816(sc[2 * j],     aH, bh2[0]);
                MMA16816(sc[2 * j + 1], aH, bh2[1]);
                MMA16816(sc[2 * j],     aH, bl2[0]);
                MMA16816(sc[2 * j + 1], aH, bl2[1]);
                MMA16816(sc[2 * j],     aL, bh2[0]);
                MMA16816(sc[2 * j + 1], aL, bh2[1]);
            }
        }

        float tm0 = -1e30f, tm1 = -1e30f;
#pragma unroll
        for (int j = 0; j < 16; j++) {
            const int col = t * 128 + j * 8 + (lane & 3) * 2;
            const float2 b0 = *(const float2*)(bias_b + (size_t)row0 * Lt + col);
            const float2 b1 = *(const float2*)(bias_b + (size_t)row1 * Lt + col);
            const float2 mk0 = *(const float2*)(mask_b + (size_t)row0 * Lt + col);
            const float2 mk1 = *(const float2*)(mask_b + (size_t)row1 * Lt + col);
            sc[j][0] = sc[j][0] * SCALE + b0.x + mk0.x;
            sc[j][1] = sc[j][1] * SCALE + b0.y + mk0.y;
            sc[j][2] = sc[j][2] * SCALE + b1.x + mk1.x;
            sc[j][3] = sc[j][3] * SCALE + b1.y + mk1.y;
            tm0 = fmaxf(tm0, fmaxf(sc[j][0], sc[j][1]));
            tm1 = fmaxf(tm1, fmaxf(sc[j][2], sc[j][3]));
        }
        tm0 = fmaxf(tm0, __shfl_xor_sync(0xffffffffu, tm0, 1));
        tm0 = fmaxf(tm0, __shfl_xor_sync(0xffffffffu, tm0, 2));
        tm1 = fmaxf(tm1, __shfl_xor_sync(0xffffffffu, tm1, 1));
        tm1 = fmaxf(tm1, __shfl_xor_sync(0xffffffffu, tm1, 2));
        const float nm0 = fmaxf(m0, tm0), nm1 = fmaxf(m1, tm1);
        const float a0 = __expf(m0 - nm0), a1 = __expf(m1 - nm1);
        float ts0 = 0.0f, ts1 = 0.0f;
#pragma unroll
        for (int j = 0; j < 16; j++) {
            sc[j][0] = __expf(sc[j][0] - nm0);
            sc[j][1] = __expf(sc[j][1] - nm0);
            sc[j][2] = __expf(sc[j][2] - nm1);
            sc[j][3] = __expf(sc[j][3] - nm1);
            ts0 += sc[j][0] + sc[j][1];
            ts1 += sc[j][2] + sc[j][3];
        }
        ts0 += __shfl_xor_sync(0xffffffffu, ts0, 1);
        ts0 += __shfl_xor_sync(0xffffffffu, ts0, 2);
        ts1 += __shfl_xor_sync(0xffffffffu, ts1, 1);
        ts1 += __shfl_xor_sync(0xffffffffu, ts1, 2);
        l0 = l0 * a0 + ts0;
        l1 = l1 * a1 + ts1;
        m0 = nm0; m1 = nm1;
#pragma unroll
        for (int g = 0; g < 8; g++) {
            o[g][0] *= a0; o[g][1] *= a0; o[g][2] *= a1; o[g][3] *= a1;
        }

#pragma unroll
        for (int ks = 0; ks < 8; ks++) {
            uint32_t pH[4], pL[4];
            {
                const float e0 = sc[2 * ks][0],     e1 = sc[2 * ks][1];
                const float e2 = sc[2 * ks][2],     e3 = sc[2 * ks][3];
                const float f0 = sc[2 * ks + 1][0], f1 = sc[2 * ks + 1][1];
                const float f2 = sc[2 * ks + 1][2], f3 = sc[2 * ks + 1][3];
                __nv_bfloat162 h0 = __floats2bfloat162_rn(e0, e1);
                __nv_bfloat162 h1 = __floats2bfloat162_rn(e2, e3);
                __nv_bfloat162 h2 = __floats2bfloat162_rn(f0, f1);
                __nv_bfloat162 h3 = __floats2bfloat162_rn(f2, f3);
                pH[0] = *(uint32_t*)&h0; pH[1] = *(uint32_t*)&h1;
                pH[2] = *(uint32_t*)&h2; pH[3] = *(uint32_t*)&h3;
                pL[0] = packbf2(e0 - __low2float(h0), e1 - __high2float(h0));
                pL[1] = packbf2(e2 - __low2float(h1), e3 - __high2float(h1));
                pL[2] = packbf2(f0 - __low2float(h2), f1 - __high2float(h2));
                pL[3] = packbf2(f2 - __low2float(h3), f3 - __high2float(h3));
            }
            const int vr = ks * 16 + (lane & 15);
#pragma unroll
            for (int g = 0; g < 4; g++) {
                const int vs = g * 2 + (lane >> 4);
                uint32_t bvh[2][2], bvl[2][2];
                LDMX4T(bvh[0][0], bvh[0][1], bvh[1][0], bvh[1][1],
                       kb + 32768 + off8(vr, vs));
                LDMX4T(bvl[0][0], bvl[0][1], bvl[1][0], bvl[1][1],
                       kb + 49152 + off8(vr, vs));
                MMA16816(o[2 * g],     pH, bvh[0]);
                MMA16816(o[2 * g + 1], pH, bvh[1]);
                MMA16816(o[2 * g],     pH, bvl[0]);
                MMA16816(o[2 * g + 1], pH, bvl[1]);
                MMA16816(o[2 * g],     pL, bvh[0]);
                MMA16816(o[2 * g + 1], pL, bvh[1]);
            }
        }

        __syncthreads();
        if (t + 2 < 8) FA_ISSUE(t + 2);
    }
#undef FA_ISSUE

    // epilogue: O/l * c_attn, fp32 store at [b,l, h*64+d]
    const float cs = c_attn[h];
    const float i0 = cs / l0, i1 = cs / l1;
    const size_t gr0 = ((size_t)(b * Lt + row0)) * Ct + h * Dt + (lane & 3) * 2;
    const size_t gr1 = ((size_t)(b * Lt + row1)) * Ct + h * Dt + (lane & 3) * 2;
#pragma unroll
    for (int g = 0; g < 8; g++) {
        float2 p0 = make_float2(o[g][0] * i0, o[g][1] * i0);
        float2 p1 = make_float2(o[g][2] * i1, o[g][3] * i1);
        *(float2*)(outp + gr0 + g * 8) = p0;
        *(float2*)(outp + gr1 + g * 8) = p1;
    }
}

// ---------------- layernorm fp32 (+residual) ----------------
template <bool RES>
__global__ __launch_bounds__(256) void ln_kernel(
    const float* __restrict__ in, const float* __restrict__ g, const float* __restrict__ be,
    const float* __restrict__ res, float* __restrict__ out, int cols)
{
    const size_t base = (size_t)blockIdx.x * cols;
    const int tid = threadIdx.x;
    __shared__ float rs[32], rs2[32];

    float s = 0.0f, s2 = 0.0f;
    for (int c = tid; c < cols; c += 256) {
        float x = in[base + c];
        s += x; s2 += x * x;
    }
#pragma unroll
    for (int o = 16; o; o >>= 1) {
        s  += __shfl_xor_sync(0xffffffffu, s,  o);
        s2 += __shfl_xor_sync(0xffffffffu, s2, o);
    }
    if ((tid & 31) == 0) { rs[tid >> 5] = s; rs2[tid >> 5] = s2; }
    __syncthreads();
    if (tid == 0) {
        float a = 0.0f, a2 = 0.0f;
        for (int i = 0; i < 8; i++) { a += rs[i]; a2 += rs2[i]; }
        rs[0] = a; rs2[0] = a2;
    }
    __syncthreads();
    const float icols = 1.0f / (float)cols;
    const float mean = rs[0] * icols;
    const float var  = rs2[0] * icols - mean * mean;
    const float rstd = rsqrtf(var + 1e-5f);

    for (int c = tid; c < cols; c += 256) {
        float x = in[base + c];
        float val = (x - mean) * rstd * g[c] + be[c];
        if (RES) val += res[base + c];
        out[base + c] = val;
    }
}

// ---------------- launch ----------------
extern "C" void kernel_launch(void* const* d_in, const int* in_sizes, int n_in,
                              void* d_out, int out_size)
{
    const float* x       = (const float*)d_in[0];
    const float* ab      = (const float*)d_in[1];
    const float* amask   = (const float*)d_in[2];
    const float* Wq      = (const float*)d_in[3];
    const float* bq      = (const float*)d_in[4];
    const float* Wk      = (const float*)d_in[5];
    const float* bk      = (const float*)d_in[6];
    const float* Wv      = (const float*)d_in[7];
    const float* bv      = (const float*)d_in[8];
    const float* Wo      = (const float*)d_in[9];
    const float* bo      = (const float*)d_in[10];
    const float* c_attn  = (const float*)d_in[11];
    const float* W1      = (const float*)d_in[12];
    const float* b1      = (const float*)d_in[13];
    const float* W2      = (const float*)d_in[14];
    const float* b2      = (const float*)d_in[15];
    const float* ln_g    = (const float*)d_in[16];
    const float* ln_b    = (const float*)d_in[17];
    const float* mln_g   = (const float*)d_in[18];
    const float* mln_b   = (const float*)d_in[19];
    const float* fln_g   = (const float*)d_in[20];
    const float* fln_b   = (const float*)d_in[21];
    const float* fmln_g  = (const float*)d_in[22];
    const float* fmln_b  = (const float*)d_in[23];
    float* out = (float*)d_out;

    float *h_, *attn_, *proj_, *x1_, *ff_;
    __nv_bfloat16 *qh, *ql, *kh, *kl, *vh, *vl;
    cudaGetSymbolAddress((void**)&h_,    g_h);
    cudaGetSymbolAddress((void**)&attn_, g_attn);
    cudaGetSymbolAddress((void**)&proj_, g_proj);
    cudaGetSymbolAddress((void**)&x1_,   g_x1);
    cudaGetSymbolAddress((void**)&ff_,   g_ff);
    cudaGetSymbolAddress((void**)&qh, g_qh);   cudaGetSymbolAddress((void**)&ql, g_ql);
    cudaGetSymbolAddress((void**)&kh, g_kh);   cudaGetSymbolAddress((void**)&kl, g_kl);
    cudaGetSymbolAddress((void**)&vh, g_vh);   cudaGetSymbolAddress((void**)&vl, g_vl);

    cudaFuncSetAttribute(tf32_gemm<EPI_BIAS>,  cudaFuncAttributeMaxDynamicSharedMemorySize, GEMM_SMEM);
    cudaFuncSetAttribute(tf32_gemm<EPI_GELU>,  cudaFuncAttributeMaxDynamicSharedMemorySize, GEMM_SMEM);
    cudaFuncSetAttribute(tf32_gemm<EPI_RES>,   cudaFuncAttributeMaxDynamicSharedMemorySize, GEMM_SMEM);
    cudaFuncSetAttribute(tf32_gemm<EPI_SPLIT>, cudaFuncAttributeMaxDynamicSharedMemorySize, GEMM_SMEM);
    cudaFuncSetAttribute(flash_attn, cudaFuncAttributeMaxDynamicSharedMemorySize, FA_SMEM);

    // ---- attention block ----
    ln_kernel<false><<<NTOK, 256>>>(x, ln_g, ln_b, nullptr, h_, Ct);

    dim3 gq(Ct / 128, NTOK / 128);   // (8, 32)
    tf32_gemm<EPI_SPLIT><<<gq, 128, GEMM_SMEM>>>(h_, Wq, bq, nullptr, nullptr, qh, ql, Ct, Ct);
    tf32_gemm<EPI_SPLIT><<<gq, 128, GEMM_SMEM>>>(h_, Wk, bk, nullptr, nullptr, kh, kl, Ct, Ct);
    tf32_gemm<EPI_SPLIT><<<gq, 128, GEMM_SMEM>>>(h_, Wv, bv, nullptr, nullptr, vh, vl, Ct, Ct);

    dim3 gfa(Lt / 128, Bb * Ht);   // (8, 64)
    flash_attn<<<gfa, 256, FA_SMEM>>>(qh, ql, kh, kl, vh, vl, ab, amask, c_attn, attn_);

    tf32_gemm<EPI_BIAS><<<gq, 128, GEMM_SMEM>>>(attn_, Wo, bo, nullptr, proj_, nullptr, nullptr, Ct, Ct);
    ln_kernel<true><<<NTOK, 256>>>(proj_, mln_g, mln_b, x, x1_, Ct);

    // ---- FFN block ----
    ln_kernel<false><<<NTOK, 256>>>(x1_, fln_g, fln_b, nullptr, h_, Ct);

    dim3 g1(FFt / 128, NTOK / 128);  // (32, 32)
    tf32_gemm<EPI_GELU><<<g1, 128, GEMM_SMEM>>>(h_, W1, b1, nullptr, ff_, nullptr, nullptr, FFt, Ct);

    ln_kernel<false><<<NTOK, 256>>>(ff_, fmln_g, fmln_b, nullptr, ff_, FFt);  // in-place

    tf32_gemm<EPI_RES><<<gq, 128, GEMM_SMEM>>>(ff_, W2, b2, x1_, out, nullptr, nullptr, Ct, FFt);
}

// round 9
// speedup vs baseline: 2.0207x; 1.0754x over previous
#include <cuda_runtime.h>
#include <cuda_bf16.h>
#include <math.h>
#include <stdint.h>

// Problem constants
#define Bb   4
#define Lt   1024
#define Ct   1024
#define Ht   16
#define Dt   64
#define FFt  4096
#define NTOK (Bb * Lt)
#define SCALE 0.08838834764831843f

// ---------------- scratch ----------------
static __device__ float g_h   [(size_t)NTOK * Ct];
static __device__ float g_attn[(size_t)NTOK * Ct];
static __device__ float g_proj[(size_t)NTOK * Ct];
static __device__ float g_x1  [(size_t)NTOK * Ct];
static __device__ float g_ff  [(size_t)NTOK * FFt];

// tf32-pre-rounded weights
static __device__ __align__(256) float g_wqr[(size_t)Ct * Ct];
static __device__ __align__(256) float g_wkr[(size_t)Ct * Ct];
static __device__ __align__(256) float g_wvr[(size_t)Ct * Ct];
static __device__ __align__(256) float g_wor[(size_t)Ct * Ct];
static __device__ __align__(256) float g_w1r[(size_t)FFt * Ct];
static __device__ __align__(256) float g_w2r[(size_t)Ct * FFt];

// split-bf16 buffers for flash attention only
static __device__ __align__(256) __nv_bfloat16 g_qh[(size_t)NTOK * Ct], g_ql[(size_t)NTOK * Ct];
static __device__ __align__(256) __nv_bfloat16 g_kh[(size_t)NTOK * Ct], g_kl[(size_t)NTOK * Ct];
static __device__ __align__(256) __nv_bfloat16 g_vh[(size_t)NTOK * Ct], g_vl[(size_t)NTOK * Ct];

__device__ __forceinline__ float gelu_exact(float x) {
    return 0.5f * x * (1.0f + erff(x * 0.70710678118654752f));
}

__device__ __forceinline__ uint32_t smem_u32(const void* p) {
    uint32_t a;
    asm("{ .reg .u64 t; cvta.to.shared.u64 t, %1; cvt.u32.u64 %0, t; }" : "=r"(a) : "l"(p));
    return a;
}

// ---------------- MMA building blocks (base sm_103 features) -------
#define LDMX4(d0, d1, d2, d3, addr) \
    asm volatile("ldmatrix.sync.aligned.m8n8.x4.shared.b16 {%0,%1,%2,%3}, [%4];" \
                 : "=r"(d0), "=r"(d1), "=r"(d2), "=r"(d3) : "r"(addr))

#define LDMX4T(d0, d1, d2, d3, addr) \
    asm volatile("ldmatrix.sync.aligned.m8n8.x4.trans.shared.b16 {%0,%1,%2,%3}, [%4];" \
                 : "=r"(d0), "=r"(d1), "=r"(d2), "=r"(d3) : "r"(addr))

#define MMA16816(d, a, b) \
    asm volatile("mma.sync.aligned.m16n8k16.row.col.f32.bf16.bf16.f32 " \
                 "{%0,%1,%2,%3}, {%4,%5,%6,%7}, {%8,%9}, {%0,%1,%2,%3};" \
                 : "+f"((d)[0]), "+f"((d)[1]), "+f"((d)[2]), "+f"((d)[3]) \
                 : "r"((a)[0]), "r"((a)[1]), "r"((a)[2]), "r"((a)[3]), \
                   "r"((b)[0]), "r"((b)[1]))

#define MMATF32(d, a, b) \
    asm volatile("mma.sync.aligned.m16n8k8.row.col.f32.tf32.tf32.f32 " \
                 "{%0,%1,%2,%3}, {%4,%5,%6,%7}, {%8,%9}, {%0,%1,%2,%3};" \
                 : "+f"((d)[0]), "+f"((d)[1]), "+f"((d)[2]), "+f"((d)[3]) \
                 : "r"((a)[0]), "r"((a)[1]), "r"((a)[2]), "r"((a)[3]), \
                   "r"((b)[0]), "r"((b)[1]))

#define CPASYNC16(saddr, gptr) \
    asm volatile("cp.async.cg.shared.global [%0], [%1], 16;" :: "r"(saddr), "l"(gptr))
#define CPCOMMIT() asm volatile("cp.async.commit_group;")
#define CPWAIT2()  asm volatile("cp.async.wait_group 2;")
#define CPWAIT1()  asm volatile("cp.async.wait_group 1;")
#define CPWAIT0()  asm volatile("cp.async.wait_group 0;")

// round-to-nearest tf32 (result is fp32 with low 13 bits zero)
__device__ __forceinline__ uint32_t rna(uint32_t x) {
    uint32_t r;
    asm("cvt.rna.tf32.f32 %0, %1;" : "=r"(r) : "f"(__uint_as_float(x)));
    return r;
}
__device__ __forceinline__ float rnaf(float x) {
    return __uint_as_float(rna(__float_as_uint(x)));
}

// 128B rows, 8x16B segs, seg' = s ^ (r&7)  -> conflict-free ldmatrix & cp.async
__device__ __forceinline__ uint32_t off8(int r, int s) {
    return (uint32_t)(r * 128 + ((s ^ (r & 7)) << 4));
}

__device__ __forceinline__ uint32_t packbf2(float x, float y) {
    __nv_bfloat162 t = __floats2bfloat162_rn(x, y);
    return *(uint32_t*)&t;
}

// ============================ tf32 dense GEMM core ===========================
// C[128,128 tile] = A @ W^T + bias (+epi). 4 warps (64x64), BK=32 fp32,
// 3-stage cp.async. A and W are PRE-ROUNDED tf32 (no in-loop cvt).
#define STAGE 32768
#define NSTAGE 3
#define GEMM_SMEM (NSTAGE * STAGE)

enum { EPI_BIAS = 0, EPI_GELU = 1, EPI_RES = 2, EPI_SPLIT = 3 };

template <int EPI>
__device__ __forceinline__ void gemm_core(
    const float* __restrict__ gA, const float* __restrict__ gW,
    const float* __restrict__ bias, const float* __restrict__ res,
    float* __restrict__ C, __nv_bfloat16* __restrict__ Chi,
    __nv_bfloat16* __restrict__ Clo, int N, int K, int brow, int bcol,
    uint32_t sb)
{
    const int tid  = threadIdx.x;
    const int lane = tid & 31;
    const int wid  = tid >> 5;
    const int wm   = (wid & 1) * 64;
    const int wn   = (wid >> 1) * 64;

    const int nch = K >> 5;
    const int s0 = tid & 7;
    const int rb = tid >> 3;
    uint32_t sw[8];
    size_t   go[8];
#pragma unroll
    for (int j = 0; j < 8; j++) {
        const int row = rb + 16 * j;
        sw[j] = off8(row, s0);
        go[j] = (size_t)row * K + s0 * 4;
    }

#define ISSUE(c)                                                              \
    do {                                                                      \
        const uint32_t bs_ = sb + ((c) % NSTAGE) * STAGE;                     \
        const size_t kof_ = (size_t)(c) * 32;                                 \
        _Pragma("unroll")                                                     \
        for (int j = 0; j < 8; j++) {                                         \
            CPASYNC16(bs_ + sw[j],         gA + go[j] + kof_);                \
            CPASYNC16(bs_ + 16384 + sw[j], gW + go[j] + kof_);                \
        }                                                                     \
        CPCOMMIT();                                                           \
    } while (0)

    ISSUE(0);
    ISSUE(1);
    ISSUE(2);

    float acc[4][8][4];
#pragma unroll
    for (int i = 0; i < 4; i++)
#pragma unroll
        for (int j = 0; j < 8; j++)
#pragma unroll
            for (int t = 0; t < 4; t++) acc[i][j][t] = 0.0f;

    for (int c = 0; c < nch; c++) {
        const int rem = nch - 1 - c;
        if (rem >= 2) CPWAIT2(); else if (rem == 1) CPWAIT1(); else CPWAIT0();
        __syncthreads();
        const uint32_t base = sb + (c % NSTAGE) * STAGE;

#pragma unroll
        for (int ks = 0; ks < 4; ks++) {
            uint32_t af[4][4], bf[8][2];
            const int ar  = wm + (lane & 15);
            const int as_ = ks * 2 + (lane >> 4);
#pragma unroll
            for (int mi = 0; mi < 4; mi++)
                LDMX4(af[mi][0], af[mi][1], af[mi][2], af[mi][3],
                      base + off8(ar + mi * 16, as_));
            const int br  = ((lane >> 4) & 1) * 8 + (lane & 7);
            const int bs2 = ks * 2 + ((lane >> 3) & 1);
#pragma unroll
            for (int np = 0; np < 4; np++)
                LDMX4(bf[np * 2][0], bf[np * 2][1], bf[np * 2 + 1][0], bf[np * 2 + 1][1],
                      base + 16384 + off8(wn + np * 16 + br, bs2));
#pragma unroll
            for (int mi = 0; mi < 4; mi++)
#pragma unroll
                for (int nt = 0; nt < 8; nt++) MMATF32(acc[mi][nt], af[mi], bf[nt]);
        }

        __syncthreads();
        if (c + 3 < nch) ISSUE(c + 3);
    }
#undef ISSUE

    const int rbase = brow * 128 + wm + (lane >> 2);
    const int cbase = bcol * 128 + wn + (lane & 3) * 2;
#pragma unroll
    for (int mi = 0; mi < 4; mi++) {
#pragma unroll
        for (int half = 0; half < 2; half++) {
            const int row = rbase + mi * 16 + half * 8;
            const size_t ro = (size_t)row * N;
#pragma unroll
            for (int nt = 0; nt < 8; nt++) {
                const int col = cbase + nt * 8;
                float v0 = acc[mi][nt][half * 2 + 0] + bias[col];
                float v1 = acc[mi][nt][half * 2 + 1] + bias[col + 1];
                if (EPI == EPI_GELU) { v0 = gelu_exact(v0); v1 = gelu_exact(v1); }
                if (EPI == EPI_RES)  { v0 += res[ro + col]; v1 += res[ro + col + 1]; }
                if (EPI == EPI_SPLIT) {
                    __nv_bfloat162 h2 = __floats2bfloat162_rn(v0, v1);
                    *(__nv_bfloat162*)(Chi + ro + col) = h2;
                    *(__nv_bfloat162*)(Clo + ro + col) =
                        __floats2bfloat162_rn(v0 - __low2float(h2), v1 - __high2float(h2));
                } else {
                    C[ro + col]     = v0;
                    C[ro + col + 1] = v1;
                }
            }
        }
    }
}

template <int EPI>
__global__ __launch_bounds__(128, 2) void tf32_gemm(
    const float* __restrict__ A, const float* __restrict__ W,
    const float* __restrict__ bias, const float* __restrict__ res,
    float* __restrict__ C, int N, int K)
{
    extern __shared__ __align__(128) char smem[];
    gemm_core<EPI>(A + (size_t)blockIdx.y * 128 * K,
                   W + (size_t)blockIdx.x * 128 * K,
                   bias, res, C, nullptr, nullptr, N, K,
                   blockIdx.y, blockIdx.x, smem_u32(smem));
}

// fused QKV: grid.x = 24 (8 N-tiles x 3 matrices), grid.y = 32
__global__ __launch_bounds__(128, 2) void tf32_gemm_qkv(
    const float* __restrict__ A,
    const float* __restrict__ Wq, const float* __restrict__ Wk, const float* __restrict__ Wv,
    const float* __restrict__ bq, const float* __restrict__ bk, const float* __restrict__ bv,
    __nv_bfloat16* __restrict__ qh, __nv_bfloat16* __restrict__ ql,
    __nv_bfloat16* __restrict__ kh, __nv_bfloat16* __restrict__ kl,
    __nv_bfloat16* __restrict__ vh, __nv_bfloat16* __restrict__ vl)
{
    extern __shared__ __align__(128) char smem[];
    const int which = blockIdx.x >> 3;
    const int nx    = blockIdx.x & 7;
    const float* W  = (which == 0) ? Wq : (which == 1) ? Wk : Wv;
    const float* bi = (which == 0) ? bq : (which == 1) ? bk : bv;
    __nv_bfloat16* hi = (which == 0) ? qh : (which == 1) ? kh : vh;
    __nv_bfloat16* lo = (which == 0) ? ql : (which == 1) ? kl : vl;
    gemm_core<EPI_SPLIT>(A + (size_t)blockIdx.y * 128 * Ct,
                         W + (size_t)nx * 128 * Ct,
                         bi, nullptr, nullptr, hi, lo, Ct, Ct,
                         blockIdx.y, nx, smem_u32(smem));
}

// ---------------- tf32 weight pre-rounding ----------------
__global__ __launch_bounds__(256) void round_w_kernel(
    const float* __restrict__ s, float* __restrict__ d, int n4)
{
    int i = blockIdx.x * 256 + threadIdx.x;
    if (i >= n4) return;
    float4 v = ((const float4*)s)[i];
    v.x = rnaf(v.x); v.y = rnaf(v.y); v.z = rnaf(v.z); v.w = rnaf(v.w);
    ((float4*)d)[i] = v;
}

// ============================ flash attention ================================
#define FA_SMEM (32768 + 2 * 65536)

__global__ __launch_bounds__(256, 1) void flash_attn(
    const __nv_bfloat16* __restrict__ qh, const __nv_bfloat16* __restrict__ ql,
    const __nv_bfloat16* __restrict__ kh, const __nv_bfloat16* __restrict__ kl,
    const __nv_bfloat16* __restrict__ vh, const __nv_bfloat16* __restrict__ vl,
    const float* __restrict__ bias, const float* __restrict__ mask,
    const float* __restrict__ c_attn, float* __restrict__ outp)
{
    extern __shared__ __align__(128) char smem[];
    const uint32_t sb = smem_u32(smem);
    const int tid  = threadIdx.x;
    const int lane = tid & 31;
    const int wid  = tid >> 5;
    const int wm   = wid * 16;
    const int b    = blockIdx.y >> 4;
    const int h    = blockIdx.y & 15;
    const int q0   = blockIdx.x * 128;

    const int lr = tid >> 1;
    const int ls = (tid & 1) * 4;
    const size_t qg  = ((size_t)(b * Lt + q0 + lr)) * Ct + h * Dt + ls * 8;
    const size_t kg0 = ((size_t)(b * Lt + lr)) * Ct + h * Dt + ls * 8;
    uint32_t ldst[4];
#pragma unroll
    for (int i = 0; i < 4; i++) ldst[i] = off8(lr, ls + i);

#pragma unroll
    for (int i = 0; i < 4; i++) {
        CPASYNC16(sb + ldst[i],         qh + qg + i * 8);
        CPASYNC16(sb + 16384 + ldst[i], ql + qg + i * 8);
    }
#define FA_ISSUE(t)                                                            \
    do {                                                                       \
        const uint32_t bs_ = sb + 32768 + ((t) & 1) * 65536;                   \
        const size_t kof_ = kg0 + (size_t)(t) * 128 * Ct;                      \
        _Pragma("unroll")                                                      \
        for (int i = 0; i < 4; i++) {                                          \
            CPASYNC16(bs_ + 0     + ldst[i], kh + kof_ + i * 8);               \
            CPASYNC16(bs_ + 16384 + ldst[i], kl + kof_ + i * 8);               \
            CPASYNC16(bs_ + 32768 + ldst[i], vh + kof_ + i * 8);               \
            CPASYNC16(bs_ + 49152 + ldst[i], vl + kof_ + i * 8);               \
        }                                                                      \
        CPCOMMIT();                                                            \
    } while (0)

    FA_ISSUE(0);
    FA_ISSUE(1);

    const float* bias_b = bias + (size_t)blockIdx.y * Lt * Lt;
    const float* mask_b = mask + (size_t)b * Lt * Lt;
    const int row0 = q0 + wm + (lane >> 2);
    const int row1 = row0 + 8;

    float m0 = -1e30f, m1 = -1e30f, l0 = 0.0f, l1 = 0.0f;
    float o[8][4];
#pragma unroll
    for (int g = 0; g < 8; g++)
#pragma unroll
        for (int t = 0; t < 4; t++) o[g][t] = 0.0f;

    for (int t = 0; t < 8; t++) {
        if (t < 7) CPWAIT1(); else CPWAIT0();
        __syncthreads();
        const uint32_t kb = sb + 32768 + (t & 1) * 65536;

        float sc[16][4];
#pragma unroll
        for (int j = 0; j < 16; j++)
#pragma unroll
            for (int e = 0; e < 4; e++) sc[j][e] = 0.0f;

#pragma unroll
        for (int ks = 0; ks < 4; ks++) {
            uint32_t aH[4], aL[4];
            const int ar = wm + (lane & 15);
            const int as_ = ks * 2 + (lane >> 4);
            LDMX4(aH[0], aH[1], aH[2], aH[3], sb + off8(ar, as_));
            LDMX4(aL[0], aL[1], aL[2], aL[3], sb + 16384 + off8(ar, as_));
            const int br = ((lane >> 4) & 1) * 8 + (lane & 7);
            const int bs2 = ks * 2 + ((lane >> 3) & 1);
#pragma unroll
            for (int j = 0; j < 8; j++) {
                uint32_t bh2[2][2], bl2[2][2];
                LDMX4(bh2[0][0], bh2[0][1], bh2[1][0], bh2[1][1],
                      kb + off8(j * 16 + br, bs2));
                LDMX4(bl2[0][0], bl2[0][1], bl2[1][0], bl2[1][1],
                      kb + 16384 + off8(j * 16 + br, bs2));
                MMA16816(sc[2 * j],     aH, bh2[0]);
                MMA16816(sc[2 * j + 1], aH, bh2[1]);
                MMA16816(sc[2 * j],     aH, bl2[0]);
                MMA16816(sc[2 * j + 1], aH, bl2[1]);
                MMA16816(sc[2 * j],     aL, bh2[0]);
                MMA16816(sc[2 * j + 1], aL, bh2[1]);
            }
        }

        float tm0 = -1e30f, tm1 = -1e30f;
#pragma unroll
        for (int j = 0; j < 16; j++) {
            const int col = t * 128 + j * 8 + (lane & 3) * 2;
            const float2 b0 = *(const float2*)(bias_b + (size_t)row0 * Lt + col);
            const float2 b1 = *(const float2*)(bias_b + (size_t)row1 * Lt + col);
            const float2 mk0 = *(const float2*)(mask_b + (size_t)row0 * Lt + col);
            const float2 mk1 = *(const float2*)(mask_b + (size_t)row1 * Lt + col);
            sc[j][0] = sc[j][0] * SCALE + b0.x + mk0.x;
            sc[j][1] = sc[j][1] * SCALE + b0.y + mk0.y;
            sc[j][2] = sc[j][2] * SCALE + b1.x + mk1.x;
            sc[j][3] = sc[j][3] * SCALE + b1.y + mk1.y;
            tm0 = fmaxf(tm0, fmaxf(sc[j][0], sc[j][1]));
            tm1 = fmaxf(tm1, fmaxf(sc[j][2], sc[j][3]));
        }
        tm0 = fmaxf(tm0, __shfl_xor_sync(0xffffffffu, tm0, 1));
        tm0 = fmaxf(tm0, __shfl_xor_sync(0xffffffffu, tm0, 2));
        tm1 = fmaxf(tm1, __shfl_xor_sync(0xffffffffu, tm1, 1));
        tm1 = fmaxf(tm1, __shfl_xor_sync(0xffffffffu, tm1, 2));
        const float nm0 = fmaxf(m0, tm0), nm1 = fmaxf(m1, tm1);
        const float a0 = __expf(m0 - nm0), a1 = __expf(m1 - nm1);
        float ts0 = 0.0f, ts1 = 0.0f;
#pragma unroll
        for (int j = 0; j < 16; j++) {
            sc[j][0] = __expf(sc[j][0] - nm0);
            sc[j][1] = __expf(sc[j][1] - nm0);
            sc[j][2] = __expf(sc[j][2] - nm1);
            sc[j][3] = __expf(sc[j][3] - nm1);
            ts0 += sc[j][0] + sc[j][1];
            ts1 += sc[j][2] + sc[j][3];
        }
        ts0 += __shfl_xor_sync(0xffffffffu, ts0, 1);
        ts0 += __shfl_xor_sync(0xffffffffu, ts0, 2);
        ts1 += __shfl_xor_sync(0xffffffffu, ts1, 1);
        ts1 += __shfl_xor_sync(0xffffffffu, ts1, 2);
        l0 = l0 * a0 + ts0;
        l1 = l1 * a1 + ts1;
        m0 = nm0; m1 = nm1;
#pragma unroll
        for (int g = 0; g < 8; g++) {
            o[g][0] *= a0; o[g][1] *= a0; o[g][2] *= a1; o[g][3] *= a1;
        }

#pragma unroll
        for (int ks = 0; ks < 8; ks++) {
            uint32_t pH[4], pL[4];
            {
                const float e0 = sc[2 * ks][0],     e1 = sc[2 * ks][1];
                const float e2 = sc[2 * ks][2],     e3 = sc[2 * ks][3];
                const float f0 = sc[2 * ks + 1][0], f1 = sc[2 * ks + 1][1];
                const float f2 = sc[2 * ks + 1][2], f3 = sc[2 * ks + 1][3];
                __nv_bfloat162 h0 = __floats2bfloat162_rn(e0, e1);
                __nv_bfloat162 h1 = __floats2bfloat162_rn(e2, e3);
                __nv_bfloat162 h2 = __floats2bfloat162_rn(f0, f1);
                __nv_bfloat162 h3 = __floats2bfloat162_rn(f2, f3);
                pH[0] = *(uint32_t*)&h0; pH[1] = *(uint32_t*)&h1;
                pH[2] = *(uint32_t*)&h2; pH[3] = *(uint32_t*)&h3;
                pL[0] = packbf2(e0 - __low2float(h0), e1 - __high2float(h0));
                pL[1] = packbf2(e2 - __low2float(h1), e3 - __high2float(h1));
                pL[2] = packbf2(f0 - __low2float(h2), f1 - __high2float(h2));
                pL[3] = packbf2(f2 - __low2float(h3), f3 - __high2float(h3));
            }
            const int vr = ks * 16 + (lane & 15);
#pragma unroll
            for (int g = 0; g < 4; g++) {
                const int vs = g * 2 + (lane >> 4);
                uint32_t bvh[2][2], bvl[2][2];
                LDMX4T(bvh[0][0], bvh[0][1], bvh[1][0], bvh[1][1],
                       kb + 32768 + off8(vr, vs));
                LDMX4T(bvl[0][0], bvl[0][1], bvl[1][0], bvl[1][1],
                       kb + 49152 + off8(vr, vs));
                MMA16816(o[2 * g],     pH, bvh[0]);
                MMA16816(o[2 * g + 1], pH, bvh[1]);
                MMA16816(o[2 * g],     pH, bvl[0]);
                MMA16816(o[2 * g + 1], pH, bvl[1]);
                MMA16816(o[2 * g],     pL, bvh[0]);
                MMA16816(o[2 * g + 1], pL, bvh[1]);
            }
        }

        __syncthreads();
        if (t + 2 < 8) FA_ISSUE(t + 2);
    }
#undef FA_ISSUE

    // epilogue: O/l * c_attn, tf32-pre-rounded fp32 store (feeds Wo GEMM)
    const float cs = c_attn[h];
    const float i0 = cs / l0, i1 = cs / l1;
    const size_t gr0 = ((size_t)(b * Lt + row0)) * Ct + h * Dt + (lane & 3) * 2;
    const size_t gr1 = ((size_t)(b * Lt + row1)) * Ct + h * Dt + (lane & 3) * 2;
#pragma unroll
    for (int g = 0; g < 8; g++) {
        float2 p0 = make_float2(rnaf(o[g][0] * i0), rnaf(o[g][1] * i0));
        float2 p1 = make_float2(rnaf(o[g][2] * i1), rnaf(o[g][3] * i1));
        *(float2*)(outp + gr0 + g * 8) = p0;
        *(float2*)(outp + gr1 + g * 8) = p1;
    }
}

// ---------------- layernorm fp32 (+residual, optional tf32-rounded out) ------
template <bool RES, bool ROUND>
__global__ __launch_bounds__(256) void ln_kernel(
    const float* __restrict__ in, const float* __restrict__ g, const float* __restrict__ be,
    const float* __restrict__ res, float* __restrict__ out, int cols)
{
    const size_t base = (size_t)blockIdx.x * cols;
    const int tid = threadIdx.x;
    __shared__ float rs[32], rs2[32];

    float s = 0.0f, s2 = 0.0f;
    for (int c = tid; c < cols; c += 256) {
        float x = in[base + c];
        s += x; s2 += x * x;
    }
#pragma unroll
    for (int o = 16; o; o >>= 1) {
        s  += __shfl_xor_sync(0xffffffffu, s,  o);
        s2 += __shfl_xor_sync(0xffffffffu, s2, o);
    }
    if ((tid & 31) == 0) { rs[tid >> 5] = s; rs2[tid >> 5] = s2; }
    __syncthreads();
    if (tid == 0) {
        float a = 0.0f, a2 = 0.0f;
        for (int i = 0; i < 8; i++) { a += rs[i]; a2 += rs2[i]; }
        rs[0] = a; rs2[0] = a2;
    }
    __syncthreads();
    const float icols = 1.0f / (float)cols;
    const float mean = rs[0] * icols;
    const float var  = rs2[0] * icols - mean * mean;
    const float rstd = rsqrtf(var + 1e-5f);

    for (int c = tid; c < cols; c += 256) {
        float x = in[base + c];
        float val = (x - mean) * rstd * g[c] + be[c];
        if (RES) val += res[base + c];
        if (ROUND) val = rnaf(val);
        out[base + c] = val;
    }
}

// ---------------- launch ----------------
extern "C" void kernel_launch(void* const* d_in, const int* in_sizes, int n_in,
                              void* d_out, int out_size)
{
    const float* x       = (const float*)d_in[0];
    const float* ab      = (const float*)d_in[1];
    const float* amask   = (const float*)d_in[2];
    const float* Wq      = (const float*)d_in[3];
    const float* bq      = (const float*)d_in[4];
    const float* Wk      = (const float*)d_in[5];
    const float* bk      = (const float*)d_in[6];
    const float* Wv      = (const float*)d_in[7];
    const float* bv      = (const float*)d_in[8];
    const float* Wo      = (const float*)d_in[9];
    const float* bo      = (const float*)d_in[10];
    const float* c_attn  = (const float*)d_in[11];
    const float* W1      = (const float*)d_in[12];
    const float* b1      = (const float*)d_in[13];
    const float* W2      = (const float*)d_in[14];
    const float* b2      = (const float*)d_in[15];
    const float* ln_g    = (const float*)d_in[16];
    const float* ln_b    = (const float*)d_in[17];
    const float* mln_g   = (const float*)d_in[18];
    const float* mln_b   = (const float*)d_in[19];
    const float* fln_g   = (const float*)d_in[20];
    const float* fln_b   = (const float*)d_in[21];
    const float* fmln_g  = (const float*)d_in[22];
    const float* fmln_b  = (const float*)d_in[23];
    float* out = (float*)d_out;

    float *h_, *attn_, *proj_, *x1_, *ff_;
    float *wqr, *wkr, *wvr, *wor, *w1r, *w2r;
    __nv_bfloat16 *qh, *ql, *kh, *kl, *vh, *vl;
    cudaGetSymbolAddress((void**)&h_,    g_h);
    cudaGetSymbolAddress((void**)&attn_, g_attn);
    cudaGetSymbolAddress((void**)&proj_, g_proj);
    cudaGetSymbolAddress((void**)&x1_,   g_x1);
    cudaGetSymbolAddress((void**)&ff_,   g_ff);
    cudaGetSymbolAddress((void**)&wqr, g_wqr);
    cudaGetSymbolAddress((void**)&wkr, g_wkr);
    cudaGetSymbolAddress((void**)&wvr, g_wvr);
    cudaGetSymbolAddress((void**)&wor, g_wor);
    cudaGetSymbolAddress((void**)&w1r, g_w1r);
    cudaGetSymbolAddress((void**)&w2r, g_w2r);
    cudaGetSymbolAddress((void**)&qh, g_qh);   cudaGetSymbolAddress((void**)&ql, g_ql);
    cudaGetSymbolAddress((void**)&kh, g_kh);   cudaGetSymbolAddress((void**)&kl, g_kl);
    cudaGetSymbolAddress((void**)&vh, g_vh);   cudaGetSymbolAddress((void**)&vl, g_vl);

    cudaFuncSetAttribute(tf32_gemm<EPI_BIAS>, cudaFuncAttributeMaxDynamicSharedMemorySize, GEMM_SMEM);
    cudaFuncSetAttribute(tf32_gemm<EPI_GELU>, cudaFuncAttributeMaxDynamicSharedMemorySize, GEMM_SMEM);
    cudaFuncSetAttribute(tf32_gemm<EPI_RES>,  cudaFuncAttributeMaxDynamicSharedMemorySize, GEMM_SMEM);
    cudaFuncSetAttribute(tf32_gemm_qkv,       cudaFuncAttributeMaxDynamicSharedMemorySize, GEMM_SMEM);
    cudaFuncSetAttribute(flash_attn, cudaFuncAttributeMaxDynamicSharedMemorySize, FA_SMEM);

    // pre-round all weights to tf32 (once per call, deterministic)
    const int nCC = Ct * Ct / 4, nFC = FFt * Ct / 4;
    round_w_kernel<<<nCC / 256, 256>>>(Wq, wqr, nCC);
    round_w_kernel<<<nCC / 256, 256>>>(Wk, wkr, nCC);
    round_w_kernel<<<nCC / 256, 256>>>(Wv, wvr, nCC);
    round_w_kernel<<<nCC / 256, 256>>>(Wo, wor, nCC);
    round_w_kernel<<<nFC / 256, 256>>>(W1, w1r, nFC);
    round_w_kernel<<<nFC / 256, 256>>>(W2, w2r, nFC);

    // ---- attention block ----
    ln_kernel<false, true><<<NTOK, 256>>>(x, ln_g, ln_b, nullptr, h_, Ct);

    dim3 gqkv(3 * Ct / 128, NTOK / 128);   // (24, 32)
    tf32_gemm_qkv<<<gqkv, 128, GEMM_SMEM>>>(h_, wqr, wkr, wvr, bq, bk, bv,
                                            qh, ql, kh, kl, vh, vl);

    dim3 gfa(Lt / 128, Bb * Ht);   // (8, 64)
    flash_attn<<<gfa, 256, FA_SMEM>>>(qh, ql, kh, kl, vh, vl, ab, amask, c_attn, attn_);

    dim3 gq(Ct / 128, NTOK / 128);   // (8, 32)
    tf32_gemm<EPI_BIAS><<<gq, 128, GEMM_SMEM>>>(attn_, wor, bo, nullptr, proj_, Ct, Ct);
    ln_kernel<true, false><<<NTOK, 256>>>(proj_, mln_g, mln_b, x, x1_, Ct);

    // ---- FFN block ----
    ln_kernel<false, true><<<NTOK, 256>>>(x1_, fln_g, fln_b, nullptr, h_, Ct);

    dim3 g1(FFt / 128, NTOK / 128);  // (32, 32)
    tf32_gemm<EPI_GELU><<<g1, 128, GEMM_SMEM>>>(h_, w1r, b1, nullptr, ff_, FFt, Ct);

    ln_kernel<false, true><<<NTOK, 256>>>(ff_, fmln_g, fmln_b, nullptr, ff_, FFt);  // in-place

    tf32_gemm<EPI_RES><<<gq, 128, GEMM_SMEM>>>(ff_, w2r, b2, x1_, out, Ct, FFt);
}